// round 1
// baseline (speedup 1.0000x reference)
#include <cuda_runtime.h>
#include <cuda_bf16.h>

// ---------------- problem constants ----------------
// B=8, C=512, H=W=96, Hh=Wh=48, Cin=256, Ci=32
#define NB   8
#define NC   512
#define NH   96
#define NW   96
#define NHW  (96*96)          // 9216
#define NCIN 256
#define NCI  32
#define NEG_INF_F (-1000000000.0f)

// ---------------- scratch ( __device__ globals, allocation-free ) ----------------
__device__ float g_hf [8L*512*96*96];   // upsampled high feature
__device__ float g_qf [8L*256*96*96];
__device__ float g_vf [8L*256*96*96];
__device__ float g_vf2[8L*256*96*96];
__device__ float g_q  [8L*32*96*96];
__device__ float g_k  [8L*32*96*96];
__device__ float g_v  [8L*256*96*96];
__device__ float g_att[8L*96*96*192];
__device__ float g_oh [8L*256*96*96];
__device__ float g_mean[512];
__device__ float g_rstd[512];

// ---------------- bilinear 2x upsample (half-pixel, edge-clamped) ----------------
__global__ void resize_kernel(const float* __restrict__ in, float* __restrict__ out) {
    long total = (long)NB * NC * NH * NW;
    for (long idx = (long)blockIdx.x * blockDim.x + threadIdx.x; idx < total;
         idx += (long)gridDim.x * blockDim.x) {
        int ox = (int)(idx % NW);
        long t  = idx / NW;
        int oy = (int)(t % NH);
        long bc = t / NH;
        int my = oy >> 1, mx = ox >> 1;
        int y0, y1, x0, x1; float wy0, wx0;
        if (oy & 1) { y0 = my;                 y1 = (my < 47) ? my + 1 : 47; wy0 = 0.75f; }
        else        { y0 = (my > 0) ? my - 1 : 0; y1 = my;                   wy0 = 0.25f; }
        if (ox & 1) { x0 = mx;                 x1 = (mx < 47) ? mx + 1 : 47; wx0 = 0.75f; }
        else        { x0 = (mx > 0) ? mx - 1 : 0; x1 = mx;                   wx0 = 0.25f; }
        const float* p = in + bc * (48 * 48);
        float v00 = p[y0*48 + x0], v01 = p[y0*48 + x1];
        float v10 = p[y1*48 + x0], v11 = p[y1*48 + x1];
        float top = wx0 * v00 + (1.0f - wx0) * v01;
        float bot = wx0 * v10 + (1.0f - wx0) * v11;
        out[idx] = wy0 * top + (1.0f - wy0) * bot;
    }
}

// ---------------- batched SGEMM:  C[b] = A(MxK) * X[b](KxN) (+bias)(+=C) ----------------
// A row-major with row stride lda. X rows contiguous (ldb = N). 64x64x16 tile, 256 thr, 4x4/thread.
__global__ void __launch_bounds__(256) sgemm_kernel(
    const float* __restrict__ A, int lda,
    const float* __restrict__ Bm, long long bStride,
    const float* __restrict__ bias,
    float* __restrict__ Cm, long long cStride,
    int M, int K, int N, int accumulate)
{
    __shared__ float As[16][68];   // As[k][m]
    __shared__ float Bs[16][68];   // Bs[k][n]
    int tid = threadIdx.x;
    int bx = blockIdx.x, by = blockIdx.y, bz = blockIdx.z;
    const float* Bb = Bm + (long long)bz * bStride;
    float* Cb = Cm + (long long)bz * cStride;

    int trow = tid >> 4, tcol = tid & 15;
    int row0 = by * 64 + trow * 4;
    int col0 = bx * 64 + tcol * 4;

    int ar = tid >> 2;            // 0..63 (m within tile)
    int ak = (tid & 3) << 2;      // 0,4,8,12
    int grow = by * 64 + ar;
    bool aval = (grow < M);
    const float* Aptr = aval ? (A + (long long)grow * lda + ak) : A;

    int bk = tid >> 4;            // 0..15 (k within tile)
    int bn = (tid & 15) << 2;     // 0..60
    const float* Bptr = Bb + (long long)bk * N + bx * 64 + bn;

    float acc[4][4];
    #pragma unroll
    for (int i = 0; i < 4; i++)
        #pragma unroll
        for (int j = 0; j < 4; j++) acc[i][j] = 0.0f;

    for (int k0 = 0; k0 < K; k0 += 16) {
        float4 av = aval ? *(const float4*)(Aptr + k0) : make_float4(0.f, 0.f, 0.f, 0.f);
        float4 bv = *(const float4*)(Bptr + (long long)k0 * N);
        As[ak + 0][ar] = av.x;
        As[ak + 1][ar] = av.y;
        As[ak + 2][ar] = av.z;
        As[ak + 3][ar] = av.w;
        *(float4*)&Bs[bk][bn] = bv;
        __syncthreads();
        #pragma unroll
        for (int kk = 0; kk < 16; kk++) {
            float4 a4 = *(const float4*)&As[kk][trow << 2];
            float4 b4 = *(const float4*)&Bs[kk][tcol << 2];
            acc[0][0] += a4.x * b4.x; acc[0][1] += a4.x * b4.y; acc[0][2] += a4.x * b4.z; acc[0][3] += a4.x * b4.w;
            acc[1][0] += a4.y * b4.x; acc[1][1] += a4.y * b4.y; acc[1][2] += a4.y * b4.z; acc[1][3] += a4.y * b4.w;
            acc[2][0] += a4.z * b4.x; acc[2][1] += a4.z * b4.y; acc[2][2] += a4.z * b4.z; acc[2][3] += a4.z * b4.w;
            acc[3][0] += a4.w * b4.x; acc[3][1] += a4.w * b4.y; acc[3][2] += a4.w * b4.z; acc[3][3] += a4.w * b4.w;
        }
        __syncthreads();
    }

    #pragma unroll
    for (int i = 0; i < 4; i++) {
        int r = row0 + i;
        if (r < M) {
            float bia = bias ? bias[r] : 0.0f;
            float4* cp = (float4*)(Cb + (long long)r * N + col0);
            float4 cv = accumulate ? *cp : make_float4(0.f, 0.f, 0.f, 0.f);
            cv.x += acc[i][0] + bia;
            cv.y += acc[i][1] + bia;
            cv.z += acc[i][2] + bia;
            cv.w += acc[i][3] + bia;
            *cp = cv;
        }
    }
}

// ---------------- eH logits: per (b,w) column-attention; diag gets NEG_INF ----------------
__global__ void __launch_bounds__(256) eH_kernel(const float* __restrict__ q,
                                                 const float* __restrict__ k,
                                                 float* __restrict__ att) {
    int w = blockIdx.x, b = blockIdx.y;
    __shared__ float Qs[32][97], Ks[32][97];
    int tid = threadIdx.x;
    for (int idx = tid; idx < 32 * 96; idx += 256) {
        int c = idx / 96, hh = idx % 96;
        long off = ((long)((b * 32 + c) * 96 + hh)) * 96 + w;
        Qs[c][hh] = q[off];
        Ks[c][hh] = k[off];
    }
    __syncthreads();
    for (int idx = tid; idx < 2304; idx += 256) {   // 96 h * 24 groups of 4 Hp
        int h = idx / 24;
        int Hp0 = (idx % 24) * 4;
        float acc[4];
        #pragma unroll
        for (int j = 0; j < 4; j++) acc[j] = (Hp0 + j == h) ? NEG_INF_F : 0.0f;
        #pragma unroll
        for (int c = 0; c < 32; c++) {
            float qv = Qs[c][h];
            #pragma unroll
            for (int j = 0; j < 4; j++) acc[j] += qv * Ks[c][Hp0 + j];
        }
        long base = (((long)(b * 96 + h) * 96 + w)) * 192 + Hp0;
        #pragma unroll
        for (int j = 0; j < 4; j++) att[base + j] = acc[j];
    }
}

// ---------------- eW logits: per (b,h) row-attention ----------------
__global__ void __launch_bounds__(256) eW_kernel(const float* __restrict__ q,
                                                 const float* __restrict__ k,
                                                 float* __restrict__ att) {
    int h = blockIdx.x, b = blockIdx.y;
    __shared__ float Qs[32][97], Ks[32][97];
    int tid = threadIdx.x;
    for (int idx = tid; idx < 32 * 96; idx += 256) {
        int c = idx / 96, ww = idx % 96;
        long off = ((long)((b * 32 + c) * 96 + h)) * 96 + ww;
        Qs[c][ww] = q[off];
        Ks[c][ww] = k[off];
    }
    __syncthreads();
    for (int idx = tid; idx < 2304; idx += 256) {
        int w = idx / 24;
        int Wp0 = (idx % 24) * 4;
        float acc[4] = {0.f, 0.f, 0.f, 0.f};
        #pragma unroll
        for (int c = 0; c < 32; c++) {
            float qv = Qs[c][w];
            #pragma unroll
            for (int j = 0; j < 4; j++) acc[j] += qv * Ks[c][Wp0 + j];
        }
        long base = (((long)(b * 96 + h) * 96 + w)) * 192 + 96 + Wp0;
        #pragma unroll
        for (int j = 0; j < 4; j++) att[base + j] = acc[j];
    }
}

// ---------------- softmax over 192-wide rows, one warp per row, in place ----------------
__global__ void softmax_kernel(float* __restrict__ att) {
    int row = blockIdx.x * blockDim.y + threadIdx.y;      // 73728 rows
    float* p = att + (long)row * 192;
    int lane = threadIdx.x;
    float v[6];
    float m = -3.0e38f;
    #pragma unroll
    for (int j = 0; j < 6; j++) { v[j] = p[j * 32 + lane]; m = fmaxf(m, v[j]); }
    #pragma unroll
    for (int o = 16; o > 0; o >>= 1) m = fmaxf(m, __shfl_xor_sync(0xffffffffu, m, o));
    float s = 0.0f;
    #pragma unroll
    for (int j = 0; j < 6; j++) { v[j] = expf(v[j] - m); s += v[j]; }
    #pragma unroll
    for (int o = 16; o > 0; o >>= 1) s += __shfl_xor_sync(0xffffffffu, s, o);
    float inv = 1.0f / s;
    #pragma unroll
    for (int j = 0; j < 6; j++) p[j * 32 + lane] = v[j] * inv;
}

// ---------------- outH: per (b,w):  out[c,h] = sum_Hp v[c,Hp] * aH[h,Hp] ----------------
#define OUT_SMEM ((96*98 + 32*97) * 4)
__global__ void __launch_bounds__(256) outH_kernel(const float* __restrict__ v,
                                                   const float* __restrict__ att,
                                                   float* __restrict__ outH) {
    extern __shared__ float sh[];
    float* Ah = sh;              // [96][98]
    float* Vs = sh + 96 * 98;    // [32][97]
    int w = blockIdx.x, b = blockIdx.y;
    int tid = threadIdx.x;
    for (int idx = tid; idx < 96 * 96; idx += 256) {
        int h = idx / 96, Hp = idx % 96;
        Ah[h * 98 + Hp] = att[(((long)(b * 96 + h) * 96 + w)) * 192 + Hp];
    }
    __syncthreads();
    int gci = tid & 7, gh = tid >> 3;
    for (int c0 = 0; c0 < 256; c0 += 32) {
        for (int idx = tid; idx < 32 * 96; idx += 256) {
            int ci = idx / 96, Hp = idx % 96;
            Vs[ci * 97 + Hp] = v[(((long)(b * 256 + c0 + ci) * 96 + Hp)) * 96 + w];
        }
        __syncthreads();
        float acc[4][3] = {};
        for (int Hp = 0; Hp < 96; Hp++) {
            float a0 = Ah[(gh * 3 + 0) * 98 + Hp];
            float a1 = Ah[(gh * 3 + 1) * 98 + Hp];
            float a2 = Ah[(gh * 3 + 2) * 98 + Hp];
            #pragma unroll
            for (int i = 0; i < 4; i++) {
                float vv = Vs[(gci * 4 + i) * 97 + Hp];
                acc[i][0] += vv * a0; acc[i][1] += vv * a1; acc[i][2] += vv * a2;
            }
        }
        #pragma unroll
        for (int i = 0; i < 4; i++)
            #pragma unroll
            for (int j = 0; j < 3; j++)
                outH[(((long)(b * 256 + c0 + gci * 4 + i) * 96 + gh * 3 + j)) * 96 + w] = acc[i][j];
        __syncthreads();
    }
}

// ------ outW + combine: per (b,h): out[c,w] = sum_Wp v[c,Wp]*aW[w,Wp];
//        dst = gamma*(outH + outW) + resid ------
__global__ void __launch_bounds__(256) outW_kernel(const float* __restrict__ v,
                                                   const float* __restrict__ att,
                                                   const float* __restrict__ outHbuf,
                                                   const float* __restrict__ resid,
                                                   const float* __restrict__ gamma_p,
                                                   float* __restrict__ dst) {
    extern __shared__ float sh[];
    float* Aw = sh;              // [96][98]
    float* Vs = sh + 96 * 98;    // [32][97]
    int h = blockIdx.x, b = blockIdx.y;
    int tid = threadIdx.x;
    float g = *gamma_p;
    for (int idx = tid; idx < 96 * 96; idx += 256) {
        int w = idx / 96, Wp = idx % 96;
        Aw[w * 98 + Wp] = att[(((long)(b * 96 + h) * 96 + w)) * 192 + 96 + Wp];
    }
    __syncthreads();
    int gci = tid & 7, gw = tid >> 3;
    for (int c0 = 0; c0 < 256; c0 += 32) {
        for (int idx = tid; idx < 32 * 96; idx += 256) {
            int ci = idx / 96, Wp = idx % 96;
            Vs[ci * 97 + Wp] = v[(((long)(b * 256 + c0 + ci) * 96 + h)) * 96 + Wp];
        }
        __syncthreads();
        float acc[4][3] = {};
        for (int Wp = 0; Wp < 96; Wp++) {
            float a0 = Aw[(gw * 3 + 0) * 98 + Wp];
            float a1 = Aw[(gw * 3 + 1) * 98 + Wp];
            float a2 = Aw[(gw * 3 + 2) * 98 + Wp];
            #pragma unroll
            for (int i = 0; i < 4; i++) {
                float vv = Vs[(gci * 4 + i) * 97 + Wp];
                acc[i][0] += vv * a0; acc[i][1] += vv * a1; acc[i][2] += vv * a2;
            }
        }
        #pragma unroll
        for (int i = 0; i < 4; i++)
            #pragma unroll
            for (int j = 0; j < 3; j++) {
                long o = ((long)(b * 256 + c0 + gci * 4 + i) * 96 + h) * 96 + gw * 3 + j;
                dst[o] = g * (outHbuf[o] + acc[i][j]) + resid[o];
            }
        __syncthreads();
    }
}

// ---------------- batchnorm stats (per channel over B,H,W) ----------------
__global__ void bn_stats_kernel(const float* __restrict__ x,
                                float* __restrict__ mean, float* __restrict__ rstd) {
    int c = blockIdx.x;  // 512
    float s = 0.0f, sq = 0.0f;
    for (int n = threadIdx.x; n < 8 * 9216; n += 256) {
        int b = n / 9216, i = n - b * 9216;
        float vv = x[((long)(b * 512 + c)) * 9216 + i];
        s += vv; sq += vv * vv;
    }
    __shared__ float sh1[256], sh2[256];
    sh1[threadIdx.x] = s; sh2[threadIdx.x] = sq;
    __syncthreads();
    for (int o = 128; o > 0; o >>= 1) {
        if (threadIdx.x < o) {
            sh1[threadIdx.x] += sh1[threadIdx.x + o];
            sh2[threadIdx.x] += sh2[threadIdx.x + o];
        }
        __syncthreads();
    }
    if (threadIdx.x == 0) {
        float m = sh1[0] / 73728.0f;
        float var = sh2[0] / 73728.0f - m * m;
        mean[c] = m;
        rstd[c] = rsqrtf(var + 1e-5f);
    }
}

// ---------------- batchnorm apply + relu (in place on d_out) ----------------
__global__ void bn_apply_kernel(float* __restrict__ x,
                                const float* __restrict__ mean, const float* __restrict__ rstd,
                                const float* __restrict__ scale, const float* __restrict__ bias) {
    long total = 8L * 512 * 9216;
    for (long idx = (long)blockIdx.x * blockDim.x + threadIdx.x; idx < total;
         idx += (long)gridDim.x * blockDim.x) {
        int c = (int)((idx / 9216) % 512);
        float vv = (x[idx] - mean[c]) * rstd[c] * scale[c] + bias[c];
        x[idx] = vv > 0.0f ? vv : 0.0f;
    }
}

// ---------------- host ----------------
static inline void launch_gemm(const float* A, int lda, const float* Bm, long long bs,
                               const float* bias, float* Cm, long long cs,
                               int M, int K, int N, int acc) {
    dim3 grid(N / 64, (M + 63) / 64, 8);
    sgemm_kernel<<<grid, 256>>>(A, lda, Bm, bs, bias, Cm, cs, M, K, N, acc);
}

extern "C" void kernel_launch(void* const* d_in, const int* in_sizes, int n_in,
                              void* d_out, int out_size) {
    const float* low      = (const float*)d_in[0];
    const float* high     = (const float*)d_in[1];
    const float* conv1_w  = (const float*)d_in[2];
    const float* conv1_b  = (const float*)d_in[3];
    const float* conv2_w  = (const float*)d_in[4];
    const float* conv2_b  = (const float*)d_in[5];
    const float* q_w      = (const float*)d_in[6];
    const float* q_b      = (const float*)d_in[7];
    const float* k_w      = (const float*)d_in[8];
    const float* k_b      = (const float*)d_in[9];
    const float* v_w      = (const float*)d_in[10];
    const float* v_b      = (const float*)d_in[11];
    const float* gamma    = (const float*)d_in[12];
    const float* bw       = (const float*)d_in[13];
    const float* bn_scale = (const float*)d_in[14];
    const float* bn_bias  = (const float*)d_in[15];
    float* out = (float*)d_out;

    float *hf, *qf, *vf, *vf2, *qb, *kb, *vb, *attp, *ohb, *meanp, *rstdp;
    cudaGetSymbolAddress((void**)&hf,   g_hf);
    cudaGetSymbolAddress((void**)&qf,   g_qf);
    cudaGetSymbolAddress((void**)&vf,   g_vf);
    cudaGetSymbolAddress((void**)&vf2,  g_vf2);
    cudaGetSymbolAddress((void**)&qb,   g_q);
    cudaGetSymbolAddress((void**)&kb,   g_k);
    cudaGetSymbolAddress((void**)&vb,   g_v);
    cudaGetSymbolAddress((void**)&attp, g_att);
    cudaGetSymbolAddress((void**)&ohb,  g_oh);
    cudaGetSymbolAddress((void**)&meanp, g_mean);
    cudaGetSymbolAddress((void**)&rstdp, g_rstd);

    cudaFuncSetAttribute(outH_kernel, cudaFuncAttributeMaxDynamicSharedMemorySize, OUT_SMEM);
    cudaFuncSetAttribute(outW_kernel, cudaFuncAttributeMaxDynamicSharedMemorySize, OUT_SMEM);

    // 1. upsample high_feature -> hf
    resize_kernel<<<4096, 256>>>(high, hf);

    // 2. qf = conv1_w x low + b1   (256x512 @ 512x9216, batch 8)
    launch_gemm(conv1_w, 512, low, 512LL * 9216, conv1_b, qf, 256LL * 9216, 256, 512, 9216, 0);
    // 3. vf = conv2_w x hf + b2
    launch_gemm(conv2_w, 512, hf, 512LL * 9216, conv2_b, vf, 256LL * 9216, 256, 512, 9216, 0);
    // 4. q = q_w x qf + q_b   (loop-invariant)
    launch_gemm(q_w, 256, qf, 256LL * 9216, q_b, qb, 32LL * 9216, 32, 256, 9216, 0);

    for (int it = 0; it < 2; it++) {
        const float* src = it ? vf2 : vf;
        float* dstp      = it ? vf  : vf2;
        // k = k_w x src + k_b ; v = v_w x src + v_b
        launch_gemm(k_w, 256, src, 256LL * 9216, k_b, kb, 32LL * 9216, 32, 256, 9216, 0);
        launch_gemm(v_w, 256, src, 256LL * 9216, v_b, vb, 256LL * 9216, 256, 256, 9216, 0);
        eH_kernel<<<dim3(96, 8), 256>>>(qb, kb, attp);
        eW_kernel<<<dim3(96, 8), 256>>>(qb, kb, attp);
        softmax_kernel<<<9216, dim3(32, 8)>>>(attp);
        outH_kernel<<<dim3(96, 8), 256, OUT_SMEM>>>(vb, attp, ohb);
        outW_kernel<<<dim3(96, 8), 256, OUT_SMEM>>>(vb, attp, ohb, src, gamma, dstp);
    }

    // bottleneck: out = bw[:, :256] x vf  +  bw[:, 256:] x hf   (512x768 split)
    launch_gemm(bw,        768, vf, 256LL * 9216, nullptr, out, 512LL * 9216, 512, 256, 9216, 0);
    launch_gemm(bw + 256,  768, hf, 512LL * 9216, nullptr, out, 512LL * 9216, 512, 512, 9216, 1);

    // batchnorm + relu
    bn_stats_kernel<<<512, 256>>>(out, meanp, rstdp);
    bn_apply_kernel<<<9216, 256>>>(out, meanp, rstdp, bn_scale, bn_bias);
}

// round 3
// speedup vs baseline: 1.5003x; 1.5003x over previous
#include <cuda_runtime.h>
#include <cuda_bf16.h>
#include <cstdint>

// ---------------- problem constants ----------------
// B=8, C=512, H=W=96, Hh=Wh=48, Cin=256, Ci=32
#define NB   8
#define NC   512
#define NH   96
#define NW   96
#define NHW  (96*96)          // 9216
#define NEG_INF_F (-1000000000.0f)

// ---------------- scratch ----------------
__device__ float g_hf [8L*512*96*96];
__device__ float g_qf [8L*256*96*96];
__device__ float g_vf [8L*256*96*96];
__device__ float g_vf2[8L*256*96*96];
__device__ float g_q  [8L*32*96*96];
__device__ float g_k  [8L*32*96*96];
__device__ float g_v  [8L*256*96*96];
__device__ float g_att[8L*96*96*192];
__device__ float g_oh [8L*256*96*96];
__device__ float g_mean[512];
__device__ float g_rstd[512];

// ---------------- bilinear 2x upsample (half-pixel, edge-clamped) ----------------
__global__ void resize_kernel(const float* __restrict__ in, float* __restrict__ out) {
    long total = (long)NB * NC * NH * NW;
    for (long idx = (long)blockIdx.x * blockDim.x + threadIdx.x; idx < total;
         idx += (long)gridDim.x * blockDim.x) {
        int ox = (int)(idx % NW);
        long t  = idx / NW;
        int oy = (int)(t % NH);
        long bc = t / NH;
        int my = oy >> 1, mx = ox >> 1;
        int y0, y1, x0, x1; float wy0, wx0;
        if (oy & 1) { y0 = my;                 y1 = (my < 47) ? my + 1 : 47; wy0 = 0.75f; }
        else        { y0 = (my > 0) ? my - 1 : 0; y1 = my;                   wy0 = 0.25f; }
        if (ox & 1) { x0 = mx;                 x1 = (mx < 47) ? mx + 1 : 47; wx0 = 0.75f; }
        else        { x0 = (mx > 0) ? mx - 1 : 0; x1 = mx;                   wx0 = 0.25f; }
        const float* p = in + bc * (48 * 48);
        float v00 = p[y0*48 + x0], v01 = p[y0*48 + x1];
        float v10 = p[y1*48 + x0], v11 = p[y1*48 + x1];
        float top = wx0 * v00 + (1.0f - wx0) * v01;
        float bot = wx0 * v10 + (1.0f - wx0) * v11;
        out[idx] = wy0 * top + (1.0f - wy0) * bot;
    }
}

// ---------------- TF32 tensor-core batched GEMM ----------------
// C[b](MxN) = A(MxK) * X[b](KxN) (+bias)(+=C). A row-major stride lda,
// X rows contiguous (ld = N). Block tile 64x128x32, 8 warps of 32x32,
// mma.sync.m16n8k8.tf32, RNA-rounded inputs, fp32 accumulate.
__device__ __forceinline__ float f2tf(float x) {
    uint32_t r;
    asm("cvt.rna.tf32.f32 %0, %1;" : "=r"(r) : "f"(x));
    return __uint_as_float(r);
}
__device__ __forceinline__ void mma_tf32(float* c, const uint32_t* a, uint32_t b0, uint32_t b1) {
    asm volatile("mma.sync.aligned.m16n8k8.row.col.f32.tf32.tf32.f32 "
                 "{%0,%1,%2,%3}, {%4,%5,%6,%7}, {%8,%9}, {%0,%1,%2,%3};"
                 : "+f"(c[0]), "+f"(c[1]), "+f"(c[2]), "+f"(c[3])
                 : "r"(a[0]), "r"(a[1]), "r"(a[2]), "r"(a[3]), "r"(b0), "r"(b1));
}

__global__ void __launch_bounds__(256) mma_gemm_kernel(
    const float* __restrict__ A, int lda,
    const float* __restrict__ Bm, long long bStride,
    const float* __restrict__ bias,
    float* __restrict__ Cm, long long cStride,
    int M, int K, int N, int accumulate)
{
    __shared__ float As[32][72];    // [k][m], pitch 72 -> frag banks 8t+g (conflict-free)
    __shared__ float Bs[32][136];   // [k][n], pitch 136 -> frag banks 8t+g

    const int tid  = threadIdx.x;
    const int warp = tid >> 5, lane = tid & 31;
    const int g = lane >> 2, tq = lane & 3;
    const int wm = (warp >> 2) * 32;        // {0,32}
    const int wn = (warp & 3) * 32;         // {0,32,64,96}
    const int m0 = blockIdx.y * 64;
    const int n0 = blockIdx.x * 128;
    const float* Bb = Bm + (long long)blockIdx.z * bStride;
    float* Cb       = Cm + (long long)blockIdx.z * cStride;

    // A staging: thread -> (row am, k-quad akq & akq+4); lanes cover m 0..31 (conflict-free STS)
    const int am  = tid & 63;
    const int akq = tid >> 6;               // 0..3
    const bool aval = (m0 + am) < M;
    const float* Ap = A + (long long)(m0 + am) * lda;
    // B staging: thread -> (k row bk, n-quads bnq+8j); 128B-coalesced
    const int bk  = tid >> 3;               // 0..31
    const int bnq = tid & 7;                // 0..7
    const float* Bp = Bb + (long long)bk * N + n0 + bnq * 4;

    float acc[2][4][4];
    #pragma unroll
    for (int mf = 0; mf < 2; mf++)
        #pragma unroll
        for (int nf = 0; nf < 4; nf++)
            #pragma unroll
            for (int i = 0; i < 4; i++) acc[mf][nf][i] = 0.0f;

    float4 aP0, aP1, bP[4];
    const int nch = K >> 5;

    // prefetch chunk 0
    {
        if (aval) {
            aP0 = *(const float4*)(Ap + akq * 4);
            aP1 = *(const float4*)(Ap + akq * 4 + 16);
        } else { aP0 = make_float4(0,0,0,0); aP1 = aP0; }
        #pragma unroll
        for (int j = 0; j < 4; j++) bP[j] = *(const float4*)(Bp + j * 32);
    }
    // store chunk 0
    {
        As[akq*4+0][am] = f2tf(aP0.x); As[akq*4+1][am] = f2tf(aP0.y);
        As[akq*4+2][am] = f2tf(aP0.z); As[akq*4+3][am] = f2tf(aP0.w);
        As[(akq+4)*4+0][am] = f2tf(aP1.x); As[(akq+4)*4+1][am] = f2tf(aP1.y);
        As[(akq+4)*4+2][am] = f2tf(aP1.z); As[(akq+4)*4+3][am] = f2tf(aP1.w);
        #pragma unroll
        for (int j = 0; j < 4; j++) {
            float4 v = bP[j];
            v.x = f2tf(v.x); v.y = f2tf(v.y); v.z = f2tf(v.z); v.w = f2tf(v.w);
            *(float4*)&Bs[bk][(bnq + 8*j) * 4] = v;
        }
    }
    __syncthreads();

    for (int c = 0; c < nch; c++) {
        // prefetch next chunk into registers
        if (c + 1 < nch) {
            int k0 = (c + 1) * 32;
            if (aval) {
                aP0 = *(const float4*)(Ap + k0 + akq * 4);
                aP1 = *(const float4*)(Ap + k0 + akq * 4 + 16);
            } else { aP0 = make_float4(0,0,0,0); aP1 = aP0; }
            #pragma unroll
            for (int j = 0; j < 4; j++) bP[j] = *(const float4*)(Bp + (long long)k0 * N + j * 32);
        }
        // compute current chunk: 4 k-steps of k=8
        #pragma unroll
        for (int ks = 0; ks < 4; ks++) {
            const int k1 = ks * 8 + tq, k2 = k1 + 4;
            uint32_t afr[2][4];
            #pragma unroll
            for (int mf = 0; mf < 2; mf++) {
                int mb = wm + mf * 16 + g;
                afr[mf][0] = __float_as_uint(As[k1][mb]);
                afr[mf][1] = __float_as_uint(As[k1][mb + 8]);
                afr[mf][2] = __float_as_uint(As[k2][mb]);
                afr[mf][3] = __float_as_uint(As[k2][mb + 8]);
            }
            #pragma unroll
            for (int nf = 0; nf < 4; nf++) {
                int nb = wn + nf * 8 + g;
                uint32_t b0 = __float_as_uint(Bs[k1][nb]);
                uint32_t b1 = __float_as_uint(Bs[k2][nb]);
                mma_tf32(acc[0][nf], afr[0], b0, b1);
                mma_tf32(acc[1][nf], afr[1], b0, b1);
            }
        }
        __syncthreads();
        if (c + 1 < nch) {
            As[akq*4+0][am] = f2tf(aP0.x); As[akq*4+1][am] = f2tf(aP0.y);
            As[akq*4+2][am] = f2tf(aP0.z); As[akq*4+3][am] = f2tf(aP0.w);
            As[(akq+4)*4+0][am] = f2tf(aP1.x); As[(akq+4)*4+1][am] = f2tf(aP1.y);
            As[(akq+4)*4+2][am] = f2tf(aP1.z); As[(akq+4)*4+3][am] = f2tf(aP1.w);
            #pragma unroll
            for (int j = 0; j < 4; j++) {
                float4 v = bP[j];
                v.x = f2tf(v.x); v.y = f2tf(v.y); v.z = f2tf(v.z); v.w = f2tf(v.w);
                *(float4*)&Bs[bk][(bnq + 8*j) * 4] = v;
            }
            __syncthreads();
        }
    }

    // epilogue: rows g / g+8 per mfrag, cols 2t,2t+1 per nfrag (float2 stores)
    #pragma unroll
    for (int mf = 0; mf < 2; mf++) {
        #pragma unroll
        for (int half = 0; half < 2; half++) {
            int r = m0 + wm + mf * 16 + g + half * 8;
            if (r < M) {
                float bia = bias ? bias[r] : 0.0f;
                #pragma unroll
                for (int nf = 0; nf < 4; nf++) {
                    int cc = n0 + wn + nf * 8 + 2 * tq;
                    float2* cp = (float2*)(Cb + (long long)r * N + cc);
                    float2 cv;
                    if (accumulate) cv = *cp; else { cv.x = 0.f; cv.y = 0.f; }
                    cv.x += acc[mf][nf][half * 2 + 0] + bia;
                    cv.y += acc[mf][nf][half * 2 + 1] + bia;
                    *cp = cv;
                }
            }
        }
    }
}

// ---------------- eH logits ----------------
__global__ void __launch_bounds__(256) eH_kernel(const float* __restrict__ q,
                                                 const float* __restrict__ k,
                                                 float* __restrict__ att) {
    int w = blockIdx.x, b = blockIdx.y;
    __shared__ float Qs[32][97], Ks[32][97];
    int tid = threadIdx.x;
    for (int idx = tid; idx < 32 * 96; idx += 256) {
        int c = idx / 96, hh = idx % 96;
        long off = ((long)((b * 32 + c) * 96 + hh)) * 96 + w;
        Qs[c][hh] = q[off];
        Ks[c][hh] = k[off];
    }
    __syncthreads();
    for (int idx = tid; idx < 2304; idx += 256) {
        int h = idx / 24;
        int Hp0 = (idx % 24) * 4;
        float acc[4];
        #pragma unroll
        for (int j = 0; j < 4; j++) acc[j] = (Hp0 + j == h) ? NEG_INF_F : 0.0f;
        #pragma unroll
        for (int c = 0; c < 32; c++) {
            float qv = Qs[c][h];
            #pragma unroll
            for (int j = 0; j < 4; j++) acc[j] += qv * Ks[c][Hp0 + j];
        }
        long base = (((long)(b * 96 + h) * 96 + w)) * 192 + Hp0;
        #pragma unroll
        for (int j = 0; j < 4; j++) att[base + j] = acc[j];
    }
}

// ---------------- eW logits ----------------
__global__ void __launch_bounds__(256) eW_kernel(const float* __restrict__ q,
                                                 const float* __restrict__ k,
                                                 float* __restrict__ att) {
    int h = blockIdx.x, b = blockIdx.y;
    __shared__ float Qs[32][97], Ks[32][97];
    int tid = threadIdx.x;
    for (int idx = tid; idx < 32 * 96; idx += 256) {
        int c = idx / 96, ww = idx % 96;
        long off = ((long)((b * 32 + c) * 96 + h)) * 96 + ww;
        Qs[c][ww] = q[off];
        Ks[c][ww] = k[off];
    }
    __syncthreads();
    for (int idx = tid; idx < 2304; idx += 256) {
        int w = idx / 24;
        int Wp0 = (idx % 24) * 4;
        float acc[4] = {0.f, 0.f, 0.f, 0.f};
        #pragma unroll
        for (int c = 0; c < 32; c++) {
            float qv = Qs[c][w];
            #pragma unroll
            for (int j = 0; j < 4; j++) acc[j] += qv * Ks[c][Wp0 + j];
        }
        long base = (((long)(b * 96 + h) * 96 + w)) * 192 + 96 + Wp0;
        #pragma unroll
        for (int j = 0; j < 4; j++) att[base + j] = acc[j];
    }
}

// ---------------- softmax over 192-wide rows ----------------
__global__ void softmax_kernel(float* __restrict__ att) {
    int row = blockIdx.x * blockDim.y + threadIdx.y;
    float* p = att + (long)row * 192;
    int lane = threadIdx.x;
    float v[6];
    float m = -3.0e38f;
    #pragma unroll
    for (int j = 0; j < 6; j++) { v[j] = p[j * 32 + lane]; m = fmaxf(m, v[j]); }
    #pragma unroll
    for (int o = 16; o > 0; o >>= 1) m = fmaxf(m, __shfl_xor_sync(0xffffffffu, m, o));
    float s = 0.0f;
    #pragma unroll
    for (int j = 0; j < 6; j++) { v[j] = expf(v[j] - m); s += v[j]; }
    #pragma unroll
    for (int o = 16; o > 0; o >>= 1) s += __shfl_xor_sync(0xffffffffu, s, o);
    float inv = 1.0f / s;
    #pragma unroll
    for (int j = 0; j < 6; j++) p[j * 32 + lane] = v[j] * inv;
}

// ---------------- outH ----------------
#define OUT_SMEM ((96*98 + 32*97) * 4)
__global__ void __launch_bounds__(256) outH_kernel(const float* __restrict__ v,
                                                   const float* __restrict__ att,
                                                   float* __restrict__ outH) {
    extern __shared__ float sh[];
    float* Ah = sh;
    float* Vs = sh + 96 * 98;
    int w = blockIdx.x, b = blockIdx.y;
    int tid = threadIdx.x;
    for (int idx = tid; idx < 96 * 96; idx += 256) {
        int h = idx / 96, Hp = idx % 96;
        Ah[h * 98 + Hp] = att[(((long)(b * 96 + h) * 96 + w)) * 192 + Hp];
    }
    __syncthreads();
    int gci = tid & 7, gh = tid >> 3;
    for (int c0 = 0; c0 < 256; c0 += 32) {
        for (int idx = tid; idx < 32 * 96; idx += 256) {
            int ci = idx / 96, Hp = idx % 96;
            Vs[ci * 97 + Hp] = v[(((long)(b * 256 + c0 + ci) * 96 + Hp)) * 96 + w];
        }
        __syncthreads();
        float acc[4][3] = {};
        for (int Hp = 0; Hp < 96; Hp++) {
            float a0 = Ah[(gh * 3 + 0) * 98 + Hp];
            float a1 = Ah[(gh * 3 + 1) * 98 + Hp];
            float a2 = Ah[(gh * 3 + 2) * 98 + Hp];
            #pragma unroll
            for (int i = 0; i < 4; i++) {
                float vv = Vs[(gci * 4 + i) * 97 + Hp];
                acc[i][0] += vv * a0; acc[i][1] += vv * a1; acc[i][2] += vv * a2;
            }
        }
        #pragma unroll
        for (int i = 0; i < 4; i++)
            #pragma unroll
            for (int j = 0; j < 3; j++)
                outH[(((long)(b * 256 + c0 + gci * 4 + i) * 96 + gh * 3 + j)) * 96 + w] = acc[i][j];
        __syncthreads();
    }
}

// ---------------- outW + combine ----------------
__global__ void __launch_bounds__(256) outW_kernel(const float* __restrict__ v,
                                                   const float* __restrict__ att,
                                                   const float* __restrict__ outHbuf,
                                                   const float* __restrict__ resid,
                                                   const float* __restrict__ gamma_p,
                                                   float* __restrict__ dst) {
    extern __shared__ float sh[];
    float* Aw = sh;
    float* Vs = sh + 96 * 98;
    int h = blockIdx.x, b = blockIdx.y;
    int tid = threadIdx.x;
    float g = *gamma_p;
    for (int idx = tid; idx < 96 * 96; idx += 256) {
        int w = idx / 96, Wp = idx % 96;
        Aw[w * 98 + Wp] = att[(((long)(b * 96 + h) * 96 + w)) * 192 + 96 + Wp];
    }
    __syncthreads();
    int gci = tid & 7, gw = tid >> 3;
    for (int c0 = 0; c0 < 256; c0 += 32) {
        for (int idx = tid; idx < 32 * 96; idx += 256) {
            int ci = idx / 96, Wp = idx % 96;
            Vs[ci * 97 + Wp] = v[(((long)(b * 256 + c0 + ci) * 96 + h)) * 96 + Wp];
        }
        __syncthreads();
        float acc[4][3] = {};
        for (int Wp = 0; Wp < 96; Wp++) {
            float a0 = Aw[(gw * 3 + 0) * 98 + Wp];
            float a1 = Aw[(gw * 3 + 1) * 98 + Wp];
            float a2 = Aw[(gw * 3 + 2) * 98 + Wp];
            #pragma unroll
            for (int i = 0; i < 4; i++) {
                float vv = Vs[(gci * 4 + i) * 97 + Wp];
                acc[i][0] += vv * a0; acc[i][1] += vv * a1; acc[i][2] += vv * a2;
            }
        }
        #pragma unroll
        for (int i = 0; i < 4; i++)
            #pragma unroll
            for (int j = 0; j < 3; j++) {
                long o = ((long)(b * 256 + c0 + gci * 4 + i) * 96 + h) * 96 + gw * 3 + j;
                dst[o] = g * (outHbuf[o] + acc[i][j]) + resid[o];
            }
        __syncthreads();
    }
}

// ---------------- batchnorm ----------------
__global__ void bn_stats_kernel(const float* __restrict__ x,
                                float* __restrict__ mean, float* __restrict__ rstd) {
    int c = blockIdx.x;
    float s = 0.0f, sq = 0.0f;
    for (int n = threadIdx.x; n < 8 * 9216; n += 256) {
        int b = n / 9216, i = n - b * 9216;
        float vv = x[((long)(b * 512 + c)) * 9216 + i];
        s += vv; sq += vv * vv;
    }
    __shared__ float sh1[256], sh2[256];
    sh1[threadIdx.x] = s; sh2[threadIdx.x] = sq;
    __syncthreads();
    for (int o = 128; o > 0; o >>= 1) {
        if (threadIdx.x < o) {
            sh1[threadIdx.x] += sh1[threadIdx.x + o];
            sh2[threadIdx.x] += sh2[threadIdx.x + o];
        }
        __syncthreads();
    }
    if (threadIdx.x == 0) {
        float m = sh1[0] / 73728.0f;
        float var = sh2[0] / 73728.0f - m * m;
        mean[c] = m;
        rstd[c] = rsqrtf(var + 1e-5f);
    }
}

__global__ void bn_apply_kernel(float* __restrict__ x,
                                const float* __restrict__ mean, const float* __restrict__ rstd,
                                const float* __restrict__ scale, const float* __restrict__ bias) {
    long total = 8L * 512 * 9216;
    for (long idx = (long)blockIdx.x * blockDim.x + threadIdx.x; idx < total;
         idx += (long)gridDim.x * blockDim.x) {
        int c = (int)((idx / 9216) % 512);
        float vv = (x[idx] - mean[c]) * rstd[c] * scale[c] + bias[c];
        x[idx] = vv > 0.0f ? vv : 0.0f;
    }
}

// ---------------- host ----------------
static inline void launch_gemm(const float* A, int lda, const float* Bm, long long bs,
                               const float* bias, float* Cm, long long cs,
                               int M, int K, int N, int acc) {
    dim3 grid(N / 128, (M + 63) / 64, 8);
    mma_gemm_kernel<<<grid, 256>>>(A, lda, Bm, bs, bias, Cm, cs, M, K, N, acc);
}

extern "C" void kernel_launch(void* const* d_in, const int* in_sizes, int n_in,
                              void* d_out, int out_size) {
    const float* low      = (const float*)d_in[0];
    const float* high     = (const float*)d_in[1];
    const float* conv1_w  = (const float*)d_in[2];
    const float* conv1_b  = (const float*)d_in[3];
    const float* conv2_w  = (const float*)d_in[4];
    const float* conv2_b  = (const float*)d_in[5];
    const float* q_w      = (const float*)d_in[6];
    const float* q_b      = (const float*)d_in[7];
    const float* k_w      = (const float*)d_in[8];
    const float* k_b      = (const float*)d_in[9];
    const float* v_w      = (const float*)d_in[10];
    const float* v_b      = (const float*)d_in[11];
    const float* gamma    = (const float*)d_in[12];
    const float* bw       = (const float*)d_in[13];
    const float* bn_scale = (const float*)d_in[14];
    const float* bn_bias  = (const float*)d_in[15];
    float* out = (float*)d_out;

    float *hf, *qf, *vf, *vf2, *qb, *kb, *vb, *attp, *ohb, *meanp, *rstdp;
    cudaGetSymbolAddress((void**)&hf,   g_hf);
    cudaGetSymbolAddress((void**)&qf,   g_qf);
    cudaGetSymbolAddress((void**)&vf,   g_vf);
    cudaGetSymbolAddress((void**)&vf2,  g_vf2);
    cudaGetSymbolAddress((void**)&qb,   g_q);
    cudaGetSymbolAddress((void**)&kb,   g_k);
    cudaGetSymbolAddress((void**)&vb,   g_v);
    cudaGetSymbolAddress((void**)&attp, g_att);
    cudaGetSymbolAddress((void**)&ohb,  g_oh);
    cudaGetSymbolAddress((void**)&meanp, g_mean);
    cudaGetSymbolAddress((void**)&rstdp, g_rstd);

    cudaFuncSetAttribute(outH_kernel, cudaFuncAttributeMaxDynamicSharedMemorySize, OUT_SMEM);
    cudaFuncSetAttribute(outW_kernel, cudaFuncAttributeMaxDynamicSharedMemorySize, OUT_SMEM);

    // 1. upsample high_feature -> hf
    resize_kernel<<<4096, 256>>>(high, hf);

    // 2. qf = conv1_w x low + b1
    launch_gemm(conv1_w, 512, low, 512LL * 9216, conv1_b, qf, 256LL * 9216, 256, 512, 9216, 0);
    // 3. vf = conv2_w x hf + b2
    launch_gemm(conv2_w, 512, hf, 512LL * 9216, conv2_b, vf, 256LL * 9216, 256, 512, 9216, 0);
    // 4. q = q_w x qf + q_b   (loop-invariant)
    launch_gemm(q_w, 256, qf, 256LL * 9216, q_b, qb, 32LL * 9216, 32, 256, 9216, 0);

    for (int it = 0; it < 2; it++) {
        const float* src = it ? vf2 : vf;
        float* dstp      = it ? vf  : vf2;
        launch_gemm(k_w, 256, src, 256LL * 9216, k_b, kb, 32LL * 9216, 32, 256, 9216, 0);
        launch_gemm(v_w, 256, src, 256LL * 9216, v_b, vb, 256LL * 9216, 256, 256, 9216, 0);
        eH_kernel<<<dim3(96, 8), 256>>>(qb, kb, attp);
        eW_kernel<<<dim3(96, 8), 256>>>(qb, kb, attp);
        softmax_kernel<<<9216, dim3(32, 8)>>>(attp);
        outH_kernel<<<dim3(96, 8), 256, OUT_SMEM>>>(vb, attp, ohb);
        outW_kernel<<<dim3(96, 8), 256, OUT_SMEM>>>(vb, attp, ohb, src, gamma, dstp);
    }

    // bottleneck: out = bw[:, :256] x vf  +  bw[:, 256:] x hf
    launch_gemm(bw,        768, vf, 256LL * 9216, nullptr, out, 512LL * 9216, 512, 256, 9216, 0);
    launch_gemm(bw + 256,  768, hf, 512LL * 9216, nullptr, out, 512LL * 9216, 512, 512, 9216, 1);

    // batchnorm + relu
    bn_stats_kernel<<<512, 256>>>(out, meanp, rstdp);
    bn_apply_kernel<<<9216, 256>>>(out, meanp, rstdp, bn_scale, bn_bias);
}

// round 4
// speedup vs baseline: 1.8283x; 1.2186x over previous
#include <cuda_runtime.h>
#include <cuda_bf16.h>
#include <cstdint>

// ---------------- problem constants ----------------
#define NB   8
#define NC   512
#define NH   96
#define NW   96
#define NEG_INF_F (-1000000000.0f)

// ---------------- scratch ----------------
__device__ float g_hf [8L*512*96*96];
__device__ float g_qf [8L*256*96*96];
__device__ float g_vf [8L*256*96*96];
__device__ float g_vf2[8L*256*96*96];
__device__ float g_q  [8L*32*96*96];
__device__ float g_k  [8L*32*96*96];
__device__ float g_v  [8L*256*96*96];
__device__ float g_att[8L*96*96*192];
__device__ float g_oh [8L*256*96*96];
__device__ float g_mean[512];
__device__ float g_rstd[512];

// ---------------- bilinear 2x upsample ----------------
__global__ void resize_kernel(const float* __restrict__ in, float* __restrict__ out) {
    long total = (long)NB * NC * NH * NW;
    for (long idx = (long)blockIdx.x * blockDim.x + threadIdx.x; idx < total;
         idx += (long)gridDim.x * blockDim.x) {
        int ox = (int)(idx % NW);
        long t  = idx / NW;
        int oy = (int)(t % NH);
        long bc = t / NH;
        int my = oy >> 1, mx = ox >> 1;
        int y0, y1, x0, x1; float wy0, wx0;
        if (oy & 1) { y0 = my;                 y1 = (my < 47) ? my + 1 : 47; wy0 = 0.75f; }
        else        { y0 = (my > 0) ? my - 1 : 0; y1 = my;                   wy0 = 0.25f; }
        if (ox & 1) { x0 = mx;                 x1 = (mx < 47) ? mx + 1 : 47; wx0 = 0.75f; }
        else        { x0 = (mx > 0) ? mx - 1 : 0; x1 = mx;                   wx0 = 0.25f; }
        const float* p = in + bc * (48 * 48);
        float v00 = p[y0*48 + x0], v01 = p[y0*48 + x1];
        float v10 = p[y1*48 + x0], v11 = p[y1*48 + x1];
        float top = wx0 * v00 + (1.0f - wx0) * v01;
        float bot = wx0 * v10 + (1.0f - wx0) * v11;
        out[idx] = wy0 * top + (1.0f - wy0) * bot;
    }
}

// ---------------- TF32 tensor-core batched GEMM (cp.async 3-stage) ----------------
// C[b](MxN) = A(MxK) * X[b](KxN) (+bias)(+=C). Block tile 128x128x32,
// 8 warps (2x4), warp tile 64x32, mma.m16n8k8.tf32 on raw fp32 bits (RZ).
#define APITCH 36
#define BPITCH 136
#define A_STG  (128*APITCH)     // 4608 floats / stage
#define B_STG  (32*BPITCH)      // 4352 floats / stage
#define GEMM_SMEM ((3*A_STG + 3*B_STG) * 4)   // 107520 bytes

__device__ __forceinline__ void cp16(uint32_t dst, const void* src, int bytes_valid) {
    asm volatile("cp.async.cg.shared.global [%0], [%1], 16, %2;"
                 :: "r"(dst), "l"(src), "r"(bytes_valid));
}
__device__ __forceinline__ void mma_tf32(float* c, const uint32_t* a, uint32_t b0, uint32_t b1) {
    asm volatile("mma.sync.aligned.m16n8k8.row.col.f32.tf32.tf32.f32 "
                 "{%0,%1,%2,%3}, {%4,%5,%6,%7}, {%8,%9}, {%0,%1,%2,%3};"
                 : "+f"(c[0]), "+f"(c[1]), "+f"(c[2]), "+f"(c[3])
                 : "r"(a[0]), "r"(a[1]), "r"(a[2]), "r"(a[3]), "r"(b0), "r"(b1));
}

__global__ void __launch_bounds__(256, 2) mma_gemm_kernel(
    const float* __restrict__ A, int lda,
    const float* __restrict__ Bm, long long bStride,
    const float* __restrict__ bias,
    float* __restrict__ Cm, long long cStride,
    int M, int K, int N, int accumulate)
{
    extern __shared__ float sm[];
    float* sA = sm;                 // 3 stages of [128][36]
    float* sB = sm + 3 * A_STG;     // 3 stages of [32][136]
    const uint32_t sA_u = (uint32_t)__cvta_generic_to_shared(sA);
    const uint32_t sB_u = (uint32_t)__cvta_generic_to_shared(sB);

    const int tid  = threadIdx.x;
    const int warp = tid >> 5, lane = tid & 31;
    const int g = lane >> 2, tq = lane & 3;
    const int wm = (warp >> 2) * 64;        // {0,64}
    const int wn = (warp & 3) * 32;         // {0,32,64,96}
    const int m0 = blockIdx.y * 128;
    const int n0 = blockIdx.x * 128;
    const float* Bb = Bm + (long long)blockIdx.z * bStride;
    float* Cb       = Cm + (long long)blockIdx.z * cStride;

    // copy mapping (per thread: 4 x 16B for A, 4 x 16B for B per chunk)
    int arow[4], ac16[4], brow[4], bc16[4], abytes[4];
    const float* aSrc[4];
    const float* bSrc[4];
    #pragma unroll
    for (int i = 0; i < 4; i++) {
        int ch = tid + 256 * i;
        arow[i] = ch >> 3;  ac16[i] = ch & 7;
        brow[i] = ch >> 5;  bc16[i] = ch & 31;
        abytes[i] = (m0 + arow[i] < M) ? 16 : 0;
        aSrc[i] = A  + (long long)(m0 + arow[i]) * lda + ac16[i] * 4;
        bSrc[i] = Bb + (long long)brow[i] * N + n0 + bc16[i] * 4;
    }

    const int nch = K >> 5;

    // prologue: issue chunks 0 and 1
    #pragma unroll
    for (int c = 0; c < 2; c++) {
        uint32_t da = sA_u + (c * A_STG) * 4;
        uint32_t db = sB_u + (c * B_STG) * 4;
        #pragma unroll
        for (int i = 0; i < 4; i++) {
            cp16(da + (arow[i] * APITCH + ac16[i] * 4) * 4, aSrc[i] + c * 32, abytes[i]);
            cp16(db + (brow[i] * BPITCH + bc16[i] * 4) * 4, bSrc[i] + (long long)(c * 32) * N, 16);
        }
        asm volatile("cp.async.commit_group;");
    }

    float acc[4][4][4];
    #pragma unroll
    for (int mf = 0; mf < 4; mf++)
        #pragma unroll
        for (int nf = 0; nf < 4; nf++)
            #pragma unroll
            for (int i = 0; i < 4; i++) acc[mf][nf][i] = 0.0f;

    for (int c = 0; c < nch; c++) {
        if (c + 1 < nch) asm volatile("cp.async.wait_group 1;");
        else             asm volatile("cp.async.wait_group 0;");
        __syncthreads();

        if (c + 2 < nch) {
            int s = (c + 2) % 3;
            int kc = (c + 2) * 32;
            uint32_t da = sA_u + (s * A_STG) * 4;
            uint32_t db = sB_u + (s * B_STG) * 4;
            #pragma unroll
            for (int i = 0; i < 4; i++) {
                cp16(da + (arow[i] * APITCH + ac16[i] * 4) * 4, aSrc[i] + kc, abytes[i]);
                cp16(db + (brow[i] * BPITCH + bc16[i] * 4) * 4, bSrc[i] + (long long)kc * N, 16);
            }
            asm volatile("cp.async.commit_group;");
        }

        const float* As_ = sA + (c % 3) * A_STG;
        const float* Bs_ = sB + (c % 3) * B_STG;
        #pragma unroll
        for (int ks = 0; ks < 4; ks++) {
            const int k1 = ks * 8 + tq, k2 = k1 + 4;
            uint32_t afr[4][4];
            #pragma unroll
            for (int mf = 0; mf < 4; mf++) {
                int mb = wm + mf * 16 + g;
                afr[mf][0] = __float_as_uint(As_[mb * APITCH + k1]);
                afr[mf][1] = __float_as_uint(As_[(mb + 8) * APITCH + k1]);
                afr[mf][2] = __float_as_uint(As_[mb * APITCH + k2]);
                afr[mf][3] = __float_as_uint(As_[(mb + 8) * APITCH + k2]);
            }
            #pragma unroll
            for (int nf = 0; nf < 4; nf++) {
                int nb = wn + nf * 8 + g;
                uint32_t b0 = __float_as_uint(Bs_[k1 * BPITCH + nb]);
                uint32_t b1 = __float_as_uint(Bs_[k2 * BPITCH + nb]);
                #pragma unroll
                for (int mf = 0; mf < 4; mf++)
                    mma_tf32(acc[mf][nf], afr[mf], b0, b1);
            }
        }
    }

    // epilogue
    #pragma unroll
    for (int mf = 0; mf < 4; mf++) {
        #pragma unroll
        for (int half = 0; half < 2; half++) {
            int r = m0 + wm + mf * 16 + g + half * 8;
            if (r < M) {
                float bia = bias ? bias[r] : 0.0f;
                #pragma unroll
                for (int nf = 0; nf < 4; nf++) {
                    int cc = n0 + wn + nf * 8 + 2 * tq;
                    float2* cp = (float2*)(Cb + (long long)r * N + cc);
                    float2 cv;
                    if (accumulate) cv = *cp; else { cv.x = 0.f; cv.y = 0.f; }
                    cv.x += acc[mf][nf][half * 2 + 0] + bia;
                    cv.y += acc[mf][nf][half * 2 + 1] + bia;
                    *cp = cv;
                }
            }
        }
    }
}

// ---------------- eH logits ----------------
__global__ void __launch_bounds__(256) eH_kernel(const float* __restrict__ q,
                                                 const float* __restrict__ k,
                                                 float* __restrict__ att) {
    int w = blockIdx.x, b = blockIdx.y;
    __shared__ float Qs[32][97], Ks[32][97];
    int tid = threadIdx.x;
    for (int idx = tid; idx < 32 * 96; idx += 256) {
        int c = idx / 96, hh = idx % 96;
        long off = ((long)((b * 32 + c) * 96 + hh)) * 96 + w;
        Qs[c][hh] = q[off];
        Ks[c][hh] = k[off];
    }
    __syncthreads();
    for (int idx = tid; idx < 2304; idx += 256) {
        int h = idx / 24;
        int Hp0 = (idx % 24) * 4;
        float acc[4];
        #pragma unroll
        for (int j = 0; j < 4; j++) acc[j] = (Hp0 + j == h) ? NEG_INF_F : 0.0f;
        #pragma unroll
        for (int c = 0; c < 32; c++) {
            float qv = Qs[c][h];
            #pragma unroll
            for (int j = 0; j < 4; j++) acc[j] += qv * Ks[c][Hp0 + j];
        }
        long base = (((long)(b * 96 + h) * 96 + w)) * 192 + Hp0;
        #pragma unroll
        for (int j = 0; j < 4; j++) att[base + j] = acc[j];
    }
}

// ---------------- eW logits ----------------
__global__ void __launch_bounds__(256) eW_kernel(const float* __restrict__ q,
                                                 const float* __restrict__ k,
                                                 float* __restrict__ att) {
    int h = blockIdx.x, b = blockIdx.y;
    __shared__ float Qs[32][97], Ks[32][97];
    int tid = threadIdx.x;
    for (int idx = tid; idx < 32 * 96; idx += 256) {
        int c = idx / 96, ww = idx % 96;
        long off = ((long)((b * 32 + c) * 96 + h)) * 96 + ww;
        Qs[c][ww] = q[off];
        Ks[c][ww] = k[off];
    }
    __syncthreads();
    for (int idx = tid; idx < 2304; idx += 256) {
        int w = idx / 24;
        int Wp0 = (idx % 24) * 4;
        float acc[4] = {0.f, 0.f, 0.f, 0.f};
        #pragma unroll
        for (int c = 0; c < 32; c++) {
            float qv = Qs[c][w];
            #pragma unroll
            for (int j = 0; j < 4; j++) acc[j] += qv * Ks[c][Wp0 + j];
        }
        long base = (((long)(b * 96 + h) * 96 + w)) * 192 + 96 + Wp0;
        #pragma unroll
        for (int j = 0; j < 4; j++) att[base + j] = acc[j];
    }
}

// ---------------- softmax over 192-wide rows ----------------
__global__ void softmax_kernel(float* __restrict__ att) {
    int row = blockIdx.x * blockDim.y + threadIdx.y;
    float* p = att + (long)row * 192;
    int lane = threadIdx.x;
    float v[6];
    float m = -3.0e38f;
    #pragma unroll
    for (int j = 0; j < 6; j++) { v[j] = p[j * 32 + lane]; m = fmaxf(m, v[j]); }
    #pragma unroll
    for (int o = 16; o > 0; o >>= 1) m = fmaxf(m, __shfl_xor_sync(0xffffffffu, m, o));
    float s = 0.0f;
    #pragma unroll
    for (int j = 0; j < 6; j++) { v[j] = expf(v[j] - m); s += v[j]; }
    #pragma unroll
    for (int o = 16; o > 0; o >>= 1) s += __shfl_xor_sync(0xffffffffu, s, o);
    float inv = 1.0f / s;
    #pragma unroll
    for (int j = 0; j < 6; j++) p[j * 32 + lane] = v[j] * inv;
}

// ---------------- outH ----------------
#define OUT_SMEM ((96*98 + 32*97) * 4)
__global__ void __launch_bounds__(256) outH_kernel(const float* __restrict__ v,
                                                   const float* __restrict__ att,
                                                   float* __restrict__ outH) {
    extern __shared__ float sh[];
    float* Ah = sh;
    float* Vs = sh + 96 * 98;
    int w = blockIdx.x, b = blockIdx.y;
    int tid = threadIdx.x;
    for (int idx = tid; idx < 96 * 96; idx += 256) {
        int h = idx / 96, Hp = idx % 96;
        Ah[h * 98 + Hp] = att[(((long)(b * 96 + h) * 96 + w)) * 192 + Hp];
    }
    __syncthreads();
    int gci = tid & 7, gh = tid >> 3;
    for (int c0 = 0; c0 < 256; c0 += 32) {
        for (int idx = tid; idx < 32 * 96; idx += 256) {
            int ci = idx / 96, Hp = idx % 96;
            Vs[ci * 97 + Hp] = v[(((long)(b * 256 + c0 + ci) * 96 + Hp)) * 96 + w];
        }
        __syncthreads();
        float acc[4][3] = {};
        for (int Hp = 0; Hp < 96; Hp++) {
            float a0 = Ah[(gh * 3 + 0) * 98 + Hp];
            float a1 = Ah[(gh * 3 + 1) * 98 + Hp];
            float a2 = Ah[(gh * 3 + 2) * 98 + Hp];
            #pragma unroll
            for (int i = 0; i < 4; i++) {
                float vv = Vs[(gci * 4 + i) * 97 + Hp];
                acc[i][0] += vv * a0; acc[i][1] += vv * a1; acc[i][2] += vv * a2;
            }
        }
        #pragma unroll
        for (int i = 0; i < 4; i++)
            #pragma unroll
            for (int j = 0; j < 3; j++)
                outH[(((long)(b * 256 + c0 + gci * 4 + i) * 96 + gh * 3 + j)) * 96 + w] = acc[i][j];
        __syncthreads();
    }
}

// ---------------- outW + combine ----------------
__global__ void __launch_bounds__(256) outW_kernel(const float* __restrict__ v,
                                                   const float* __restrict__ att,
                                                   const float* __restrict__ outHbuf,
                                                   const float* __restrict__ resid,
                                                   const float* __restrict__ gamma_p,
                                                   float* __restrict__ dst) {
    extern __shared__ float sh[];
    float* Aw = sh;
    float* Vs = sh + 96 * 98;
    int h = blockIdx.x, b = blockIdx.y;
    int tid = threadIdx.x;
    float g = *gamma_p;
    for (int idx = tid; idx < 96 * 96; idx += 256) {
        int w = idx / 96, Wp = idx % 96;
        Aw[w * 98 + Wp] = att[(((long)(b * 96 + h) * 96 + w)) * 192 + 96 + Wp];
    }
    __syncthreads();
    int gci = tid & 7, gw = tid >> 3;
    for (int c0 = 0; c0 < 256; c0 += 32) {
        for (int idx = tid; idx < 32 * 96; idx += 256) {
            int ci = idx / 96, Wp = idx % 96;
            Vs[ci * 97 + Wp] = v[(((long)(b * 256 + c0 + ci) * 96 + h)) * 96 + Wp];
        }
        __syncthreads();
        float acc[4][3] = {};
        for (int Wp = 0; Wp < 96; Wp++) {
            float a0 = Aw[(gw * 3 + 0) * 98 + Wp];
            float a1 = Aw[(gw * 3 + 1) * 98 + Wp];
            float a2 = Aw[(gw * 3 + 2) * 98 + Wp];
            #pragma unroll
            for (int i = 0; i < 4; i++) {
                float vv = Vs[(gci * 4 + i) * 97 + Wp];
                acc[i][0] += vv * a0; acc[i][1] += vv * a1; acc[i][2] += vv * a2;
            }
        }
        #pragma unroll
        for (int i = 0; i < 4; i++)
            #pragma unroll
            for (int j = 0; j < 3; j++) {
                long o = ((long)(b * 256 + c0 + gci * 4 + i) * 96 + h) * 96 + gw * 3 + j;
                dst[o] = g * (outHbuf[o] + acc[i][j]) + resid[o];
            }
        __syncthreads();
    }
}

// ---------------- batchnorm ----------------
__global__ void bn_stats_kernel(const float* __restrict__ x,
                                float* __restrict__ mean, float* __restrict__ rstd) {
    int c = blockIdx.x;
    float s = 0.0f, sq = 0.0f;
    for (int n = threadIdx.x; n < 8 * 9216; n += 256) {
        int b = n / 9216, i = n - b * 9216;
        float vv = x[((long)(b * 512 + c)) * 9216 + i];
        s += vv; sq += vv * vv;
    }
    __shared__ float sh1[256], sh2[256];
    sh1[threadIdx.x] = s; sh2[threadIdx.x] = sq;
    __syncthreads();
    for (int o = 128; o > 0; o >>= 1) {
        if (threadIdx.x < o) {
            sh1[threadIdx.x] += sh1[threadIdx.x + o];
            sh2[threadIdx.x] += sh2[threadIdx.x + o];
        }
        __syncthreads();
    }
    if (threadIdx.x == 0) {
        float m = sh1[0] / 73728.0f;
        float var = sh2[0] / 73728.0f - m * m;
        mean[c] = m;
        rstd[c] = rsqrtf(var + 1e-5f);
    }
}

__global__ void bn_apply_kernel(float* __restrict__ x,
                                const float* __restrict__ mean, const float* __restrict__ rstd,
                                const float* __restrict__ scale, const float* __restrict__ bias) {
    long total = 8L * 512 * 9216;
    for (long idx = (long)blockIdx.x * blockDim.x + threadIdx.x; idx < total;
         idx += (long)gridDim.x * blockDim.x) {
        int c = (int)((idx / 9216) % 512);
        float vv = (x[idx] - mean[c]) * rstd[c] * scale[c] + bias[c];
        x[idx] = vv > 0.0f ? vv : 0.0f;
    }
}

// ---------------- host ----------------
static inline void launch_gemm(const float* A, int lda, const float* Bm, long long bs,
                               const float* bias, float* Cm, long long cs,
                               int M, int K, int N, int acc) {
    dim3 grid(N / 128, (M + 127) / 128, 8);
    mma_gemm_kernel<<<grid, 256, GEMM_SMEM>>>(A, lda, Bm, bs, bias, Cm, cs, M, K, N, acc);
}

extern "C" void kernel_launch(void* const* d_in, const int* in_sizes, int n_in,
                              void* d_out, int out_size) {
    const float* low      = (const float*)d_in[0];
    const float* high     = (const float*)d_in[1];
    const float* conv1_w  = (const float*)d_in[2];
    const float* conv1_b  = (const float*)d_in[3];
    const float* conv2_w  = (const float*)d_in[4];
    const float* conv2_b  = (const float*)d_in[5];
    const float* q_w      = (const float*)d_in[6];
    const float* q_b      = (const float*)d_in[7];
    const float* k_w      = (const float*)d_in[8];
    const float* k_b      = (const float*)d_in[9];
    const float* v_w      = (const float*)d_in[10];
    const float* v_b      = (const float*)d_in[11];
    const float* gamma    = (const float*)d_in[12];
    const float* bw       = (const float*)d_in[13];
    const float* bn_scale = (const float*)d_in[14];
    const float* bn_bias  = (const float*)d_in[15];
    float* out = (float*)d_out;

    float *hf, *qf, *vf, *vf2, *qb, *kb, *vb, *attp, *ohb, *meanp, *rstdp;
    cudaGetSymbolAddress((void**)&hf,   g_hf);
    cudaGetSymbolAddress((void**)&qf,   g_qf);
    cudaGetSymbolAddress((void**)&vf,   g_vf);
    cudaGetSymbolAddress((void**)&vf2,  g_vf2);
    cudaGetSymbolAddress((void**)&qb,   g_q);
    cudaGetSymbolAddress((void**)&kb,   g_k);
    cudaGetSymbolAddress((void**)&vb,   g_v);
    cudaGetSymbolAddress((void**)&attp, g_att);
    cudaGetSymbolAddress((void**)&ohb,  g_oh);
    cudaGetSymbolAddress((void**)&meanp, g_mean);
    cudaGetSymbolAddress((void**)&rstdp, g_rstd);

    cudaFuncSetAttribute(mma_gemm_kernel, cudaFuncAttributeMaxDynamicSharedMemorySize, GEMM_SMEM);
    cudaFuncSetAttribute(outH_kernel, cudaFuncAttributeMaxDynamicSharedMemorySize, OUT_SMEM);
    cudaFuncSetAttribute(outW_kernel, cudaFuncAttributeMaxDynamicSharedMemorySize, OUT_SMEM);

    // 1. upsample high_feature -> hf
    resize_kernel<<<4096, 256>>>(high, hf);

    // 2. qf = conv1_w x low + b1
    launch_gemm(conv1_w, 512, low, 512LL * 9216, conv1_b, qf, 256LL * 9216, 256, 512, 9216, 0);
    // 3. vf = conv2_w x hf + b2
    launch_gemm(conv2_w, 512, hf, 512LL * 9216, conv2_b, vf, 256LL * 9216, 256, 512, 9216, 0);
    // 4. q = q_w x qf + q_b   (loop-invariant)
    launch_gemm(q_w, 256, qf, 256LL * 9216, q_b, qb, 32LL * 9216, 32, 256, 9216, 0);

    for (int it = 0; it < 2; it++) {
        const float* src = it ? vf2 : vf;
        float* dstp      = it ? vf  : vf2;
        launch_gemm(k_w, 256, src, 256LL * 9216, k_b, kb, 32LL * 9216, 32, 256, 9216, 0);
        launch_gemm(v_w, 256, src, 256LL * 9216, v_b, vb, 256LL * 9216, 256, 256, 9216, 0);
        eH_kernel<<<dim3(96, 8), 256>>>(qb, kb, attp);
        eW_kernel<<<dim3(96, 8), 256>>>(qb, kb, attp);
        softmax_kernel<<<9216, dim3(32, 8)>>>(attp);
        outH_kernel<<<dim3(96, 8), 256, OUT_SMEM>>>(vb, attp, ohb);
        outW_kernel<<<dim3(96, 8), 256, OUT_SMEM>>>(vb, attp, ohb, src, gamma, dstp);
    }

    // bottleneck: out = bw[:, :256] x vf  +  bw[:, 256:] x hf
    launch_gemm(bw,        768, vf, 256LL * 9216, nullptr, out, 512LL * 9216, 512, 256, 9216, 0);
    launch_gemm(bw + 256,  768, hf, 512LL * 9216, nullptr, out, 512LL * 9216, 512, 512, 9216, 1);

    // batchnorm + relu
    bn_stats_kernel<<<512, 256>>>(out, meanp, rstdp);
    bn_apply_kernel<<<9216, 256>>>(out, meanp, rstdp, bn_scale, bn_bias);
}

// round 5
// speedup vs baseline: 1.8375x; 1.0051x over previous
#include <cuda_runtime.h>
#include <cuda_bf16.h>
#include <cstdint>

// ---------------- problem constants ----------------
#define NB   8
#define NC   512
#define NH   96
#define NW   96
#define NEG_INF_F (-1000000000.0f)

// ---------------- scratch ----------------
__device__ float g_hf [8L*512*96*96];
__device__ float g_qf [8L*256*96*96];
__device__ float g_vf [8L*256*96*96];
__device__ float g_vf2[8L*256*96*96];
__device__ float g_q  [8L*32*96*96];
__device__ float g_k  [8L*32*96*96];
__device__ float g_v  [8L*256*96*96];
__device__ float g_qt [8L*32*96*96];
__device__ float g_kt [8L*32*96*96];
__device__ float g_vt [8L*256*96*96];
__device__ float g_attH[8L*96*96*96];
__device__ float g_attW[8L*96*96*96];
__device__ float g_oh [8L*256*96*96];   // ohT: [b][c][w][h]
__device__ float g_ow [8L*256*96*96];   // ow : [b][c][h][w]
__device__ float g_mean[512];
__device__ float g_rstd[512];

// ---------------- bilinear 2x upsample ----------------
__global__ void resize_kernel(const float* __restrict__ in, float* __restrict__ out) {
    long total = (long)NB * NC * NH * NW;
    for (long idx = (long)blockIdx.x * blockDim.x + threadIdx.x; idx < total;
         idx += (long)gridDim.x * blockDim.x) {
        int ox = (int)(idx % NW);
        long t  = idx / NW;
        int oy = (int)(t % NH);
        long bc = t / NH;
        int my = oy >> 1, mx = ox >> 1;
        int y0, y1, x0, x1; float wy0, wx0;
        if (oy & 1) { y0 = my;                 y1 = (my < 47) ? my + 1 : 47; wy0 = 0.75f; }
        else        { y0 = (my > 0) ? my - 1 : 0; y1 = my;                   wy0 = 0.25f; }
        if (ox & 1) { x0 = mx;                 x1 = (mx < 47) ? mx + 1 : 47; wx0 = 0.75f; }
        else        { x0 = (mx > 0) ? mx - 1 : 0; x1 = mx;                   wx0 = 0.25f; }
        const float* p = in + bc * (48 * 48);
        float v00 = p[y0*48 + x0], v01 = p[y0*48 + x1];
        float v10 = p[y1*48 + x0], v11 = p[y1*48 + x1];
        float top = wx0 * v00 + (1.0f - wx0) * v01;
        float bot = wx0 * v10 + (1.0f - wx0) * v11;
        out[idx] = wy0 * top + (1.0f - wy0) * bot;
    }
}

// ---------------- TF32 tensor-core batched GEMM (cp.async 3-stage) ----------------
#define APITCH 36
#define BPITCH 136
#define A_STG  (128*APITCH)
#define B_STG  (32*BPITCH)
#define GEMM_SMEM ((3*A_STG + 3*B_STG) * 4)

__device__ __forceinline__ void cp16(uint32_t dst, const void* src, int bytes_valid) {
    asm volatile("cp.async.cg.shared.global [%0], [%1], 16, %2;"
                 :: "r"(dst), "l"(src), "r"(bytes_valid));
}
__device__ __forceinline__ void mma_tf32(float* c, const uint32_t* a, uint32_t b0, uint32_t b1) {
    asm volatile("mma.sync.aligned.m16n8k8.row.col.f32.tf32.tf32.f32 "
                 "{%0,%1,%2,%3}, {%4,%5,%6,%7}, {%8,%9}, {%0,%1,%2,%3};"
                 : "+f"(c[0]), "+f"(c[1]), "+f"(c[2]), "+f"(c[3])
                 : "r"(a[0]), "r"(a[1]), "r"(a[2]), "r"(a[3]), "r"(b0), "r"(b1));
}

__global__ void __launch_bounds__(256, 2) mma_gemm_kernel(
    const float* __restrict__ A, int lda,
    const float* __restrict__ Bm, long long bStride,
    const float* __restrict__ bias,
    float* __restrict__ Cm, long long cStride,
    int M, int K, int N, int accumulate)
{
    extern __shared__ float sm[];
    float* sA = sm;
    float* sB = sm + 3 * A_STG;
    const uint32_t sA_u = (uint32_t)__cvta_generic_to_shared(sA);
    const uint32_t sB_u = (uint32_t)__cvta_generic_to_shared(sB);

    const int tid  = threadIdx.x;
    const int warp = tid >> 5, lane = tid & 31;
    const int g = lane >> 2, tq = lane & 3;
    const int wm = (warp >> 2) * 64;
    const int wn = (warp & 3) * 32;
    const int m0 = blockIdx.y * 128;
    const int n0 = blockIdx.x * 128;
    const float* Bb = Bm + (long long)blockIdx.z * bStride;
    float* Cb       = Cm + (long long)blockIdx.z * cStride;

    int arow[4], ac16[4], brow[4], bc16[4], abytes[4];
    const float* aSrc[4];
    const float* bSrc[4];
    #pragma unroll
    for (int i = 0; i < 4; i++) {
        int ch = tid + 256 * i;
        arow[i] = ch >> 3;  ac16[i] = ch & 7;
        brow[i] = ch >> 5;  bc16[i] = ch & 31;
        abytes[i] = (m0 + arow[i] < M) ? 16 : 0;
        aSrc[i] = A  + (long long)(m0 + arow[i]) * lda + ac16[i] * 4;
        bSrc[i] = Bb + (long long)brow[i] * N + n0 + bc16[i] * 4;
    }

    const int nch = K >> 5;

    #pragma unroll
    for (int c = 0; c < 2; c++) {
        uint32_t da = sA_u + (c * A_STG) * 4;
        uint32_t db = sB_u + (c * B_STG) * 4;
        #pragma unroll
        for (int i = 0; i < 4; i++) {
            cp16(da + (arow[i] * APITCH + ac16[i] * 4) * 4, aSrc[i] + c * 32, abytes[i]);
            cp16(db + (brow[i] * BPITCH + bc16[i] * 4) * 4, bSrc[i] + (long long)(c * 32) * N, 16);
        }
        asm volatile("cp.async.commit_group;");
    }

    float acc[4][4][4];
    #pragma unroll
    for (int mf = 0; mf < 4; mf++)
        #pragma unroll
        for (int nf = 0; nf < 4; nf++)
            #pragma unroll
            for (int i = 0; i < 4; i++) acc[mf][nf][i] = 0.0f;

    for (int c = 0; c < nch; c++) {
        if (c + 1 < nch) asm volatile("cp.async.wait_group 1;");
        else             asm volatile("cp.async.wait_group 0;");
        __syncthreads();

        if (c + 2 < nch) {
            int s = (c + 2) % 3;
            int kc = (c + 2) * 32;
            uint32_t da = sA_u + (s * A_STG) * 4;
            uint32_t db = sB_u + (s * B_STG) * 4;
            #pragma unroll
            for (int i = 0; i < 4; i++) {
                cp16(da + (arow[i] * APITCH + ac16[i] * 4) * 4, aSrc[i] + kc, abytes[i]);
                cp16(db + (brow[i] * BPITCH + bc16[i] * 4) * 4, bSrc[i] + (long long)kc * N, 16);
            }
            asm volatile("cp.async.commit_group;");
        }

        const float* As_ = sA + (c % 3) * A_STG;
        const float* Bs_ = sB + (c % 3) * B_STG;
        #pragma unroll
        for (int ks = 0; ks < 4; ks++) {
            const int k1 = ks * 8 + tq, k2 = k1 + 4;
            uint32_t afr[4][4];
            #pragma unroll
            for (int mf = 0; mf < 4; mf++) {
                int mb = wm + mf * 16 + g;
                afr[mf][0] = __float_as_uint(As_[mb * APITCH + k1]);
                afr[mf][1] = __float_as_uint(As_[(mb + 8) * APITCH + k1]);
                afr[mf][2] = __float_as_uint(As_[mb * APITCH + k2]);
                afr[mf][3] = __float_as_uint(As_[(mb + 8) * APITCH + k2]);
            }
            #pragma unroll
            for (int nf = 0; nf < 4; nf++) {
                int nb = wn + nf * 8 + g;
                uint32_t b0 = __float_as_uint(Bs_[k1 * BPITCH + nb]);
                uint32_t b1 = __float_as_uint(Bs_[k2 * BPITCH + nb]);
                #pragma unroll
                for (int mf = 0; mf < 4; mf++)
                    mma_tf32(acc[mf][nf], afr[mf], b0, b1);
            }
        }
    }

    #pragma unroll
    for (int mf = 0; mf < 4; mf++) {
        #pragma unroll
        for (int half = 0; half < 2; half++) {
            int r = m0 + wm + mf * 16 + g + half * 8;
            if (r < M) {
                float bia = bias ? bias[r] : 0.0f;
                #pragma unroll
                for (int nf = 0; nf < 4; nf++) {
                    int cc = n0 + wn + nf * 8 + 2 * tq;
                    float2* cp = (float2*)(Cb + (long long)r * N + cc);
                    float2 cv;
                    if (accumulate) cv = *cp; else { cv.x = 0.f; cv.y = 0.f; }
                    cv.x += acc[mf][nf][half * 2 + 0] + bia;
                    cv.y += acc[mf][nf][half * 2 + 1] + bia;
                    *cp = cv;
                }
            }
        }
    }
}

// ---------------- tiled 96x96 plane transpose ----------------
__global__ void transpose96_kernel(const float* __restrict__ in, float* __restrict__ out) {
    __shared__ float tile[32][33];
    int x0 = blockIdx.x * 32, y0 = blockIdx.y * 32;
    long base = (long)blockIdx.z * 9216;
    int tx = threadIdx.x, ty = threadIdx.y;
    #pragma unroll
    for (int k = 0; k < 4; k++)
        tile[ty + 8*k][tx] = in[base + (long)(y0 + ty + 8*k) * 96 + x0 + tx];
    __syncthreads();
    #pragma unroll
    for (int k = 0; k < 4; k++)
        out[base + (long)(x0 + ty + 8*k) * 96 + y0 + tx] = tile[tx][ty + 8*k];
}

// ---------------- qk logits (eH with diag / eW) ----------------
// block (x = w-or-h, b). qsrc/ksrc layout: ((b*32+ci)*96 + x)*96 + inner (contiguous).
// writes attX[((b*96+x)*96 + outer)*96 + inner2] (contiguous block region).
__global__ void __launch_bounds__(256) qk_kernel(const float* __restrict__ qsrc,
                                                 const float* __restrict__ ksrc,
                                                 float* __restrict__ attX, int diag) {
    int x = blockIdx.x, b = blockIdx.y;
    __shared__ float Qs[32][97], Ks[32][97];
    int tid = threadIdx.x;
    for (int idx = tid; idx < 3072; idx += 256) {
        int ci = idx / 96, inner = idx % 96;
        long off = ((long)((b * 32 + ci) * 96 + x)) * 96 + inner;
        Qs[ci][inner] = qsrc[off];
        Ks[ci][inner] = ksrc[off];
    }
    __syncthreads();
    float* ab = attX + ((long)(b * 96 + x)) * 9216;
    for (int idx = tid; idx < 2304; idx += 256) {
        int o = idx / 24;
        int P0 = (idx % 24) * 4;
        float acc[4];
        #pragma unroll
        for (int j = 0; j < 4; j++) acc[j] = (diag && (P0 + j == o)) ? NEG_INF_F : 0.0f;
        #pragma unroll
        for (int c = 0; c < 32; c++) {
            float qv = Qs[c][o];
            #pragma unroll
            for (int j = 0; j < 4; j++) acc[j] += qv * Ks[c][P0 + j];
        }
        *(float4*)(ab + o * 96 + P0) = make_float4(acc[0], acc[1], acc[2], acc[3]);
    }
}

// ---------------- joint softmax over attH row + attW row ----------------
__global__ void softmax2_kernel(float* __restrict__ attH, float* __restrict__ attW) {
    int row = blockIdx.x * 8 + threadIdx.y;          // 73728 rows
    int b = row / 9216, rem = row % 9216, h = rem / 96, w = rem % 96;
    float* pH = attH + ((long)(b * 96 + w) * 96 + h) * 96;
    float* pW = attW + ((long)(b * 96 + h) * 96 + w) * 96;
    int lane = threadIdx.x;
    float v[6];
    #pragma unroll
    for (int j = 0; j < 3; j++) v[j]     = pH[j * 32 + lane];
    #pragma unroll
    for (int j = 0; j < 3; j++) v[3 + j] = pW[j * 32 + lane];
    float m = -3.0e38f;
    #pragma unroll
    for (int j = 0; j < 6; j++) m = fmaxf(m, v[j]);
    #pragma unroll
    for (int o = 16; o > 0; o >>= 1) m = fmaxf(m, __shfl_xor_sync(0xffffffffu, m, o));
    float s = 0.0f;
    #pragma unroll
    for (int j = 0; j < 6; j++) { v[j] = expf(v[j] - m); s += v[j]; }
    #pragma unroll
    for (int o = 16; o > 0; o >>= 1) s += __shfl_xor_sync(0xffffffffu, s, o);
    float inv = 1.0f / s;
    #pragma unroll
    for (int j = 0; j < 3; j++) pH[j * 32 + lane] = v[j] * inv;
    #pragma unroll
    for (int j = 0; j < 3; j++) pW[j * 32 + lane] = v[3 + j] * inv;
}

// ---------------- P*V via tensor cores ----------------
// block (x, b): out[c][n] = sum_k Vsrc[c][k] * attX[n][k]; M=256,N=96,K=96.
// Vsrc rows at ((b*256+c)*96 + x)*96 (stride 9216); attX block region contiguous.
// out rows at ((b*256+c)*96 + x)*96. 8 warps: 2(M:64) x 4(N:24).
#define PV_SMEM ((96*100 + 128*100) * 4)
__global__ void __launch_bounds__(256) pv_mma_kernel(const float* __restrict__ Vsrc,
                                                     const float* __restrict__ attX,
                                                     float* __restrict__ outX) {
    extern __shared__ float sh[];
    float* Ah = sh;              // [96][100]
    float* Vs = sh + 96 * 100;   // [128][100]
    int x = blockIdx.x, b = blockIdx.y;
    int tid = threadIdx.x;
    int warp = tid >> 5, lane = tid & 31;
    int g = lane >> 2, tq = lane & 3;
    int wm = (warp >> 2) * 64;
    int wn = (warp & 3) * 24;

    const float* ab = attX + ((long)(b * 96 + x)) * 9216;
    for (int i4 = tid; i4 < 96 * 24; i4 += 256) {
        int h = i4 / 24, f = i4 % 24;
        float4 v4 = *(const float4*)(ab + i4 * 4);
        *(float4*)&Ah[h * 100 + f * 4] = v4;
    }

    #pragma unroll
    for (int half = 0; half < 2; half++) {
        const float* vb = Vsrc + (((long)(b * 256 + half * 128)) * 96 + x) * 96;
        for (int i4 = tid; i4 < 128 * 24; i4 += 256) {
            int ci = i4 / 24, f = i4 % 24;
            float4 v4 = *(const float4*)(vb + (long)ci * 9216 + f * 4);
            *(float4*)&Vs[ci * 100 + f * 4] = v4;
        }
        __syncthreads();

        float acc[4][3][4];
        #pragma unroll
        for (int mf = 0; mf < 4; mf++)
            #pragma unroll
            for (int nf = 0; nf < 3; nf++)
                #pragma unroll
                for (int i = 0; i < 4; i++) acc[mf][nf][i] = 0.0f;

        #pragma unroll
        for (int ks = 0; ks < 12; ks++) {
            int k1 = ks * 8 + tq, k2 = k1 + 4;
            uint32_t afr[4][4];
            #pragma unroll
            for (int mf = 0; mf < 4; mf++) {
                int mb = wm + mf * 16 + g;
                afr[mf][0] = __float_as_uint(Vs[mb * 100 + k1]);
                afr[mf][1] = __float_as_uint(Vs[(mb + 8) * 100 + k1]);
                afr[mf][2] = __float_as_uint(Vs[mb * 100 + k2]);
                afr[mf][3] = __float_as_uint(Vs[(mb + 8) * 100 + k2]);
            }
            #pragma unroll
            for (int nf = 0; nf < 3; nf++) {
                int nb = wn + nf * 8 + g;
                uint32_t b0 = __float_as_uint(Ah[nb * 100 + k1]);
                uint32_t b1 = __float_as_uint(Ah[nb * 100 + k2]);
                #pragma unroll
                for (int mf = 0; mf < 4; mf++)
                    mma_tf32(acc[mf][nf], afr[mf], b0, b1);
            }
        }
        __syncthreads();   // all warps done reading Vs before next half overwrites

        #pragma unroll
        for (int mf = 0; mf < 4; mf++) {
            #pragma unroll
            for (int hm = 0; hm < 2; hm++) {
                int c = half * 128 + wm + mf * 16 + g + hm * 8;
                float* orow = outX + (((long)(b * 256 + c)) * 96 + x) * 96;
                #pragma unroll
                for (int nf = 0; nf < 3; nf++) {
                    int col = wn + nf * 8 + 2 * tq;
                    float2 cv;
                    cv.x = acc[mf][nf][hm * 2 + 0];
                    cv.y = acc[mf][nf][hm * 2 + 1];
                    *(float2*)(orow + col) = cv;
                }
            }
        }
    }
}

// ---------------- combine: dst = gamma*(ow + ohT^T) + resid ----------------
__global__ void combine_kernel(const float* __restrict__ ow, const float* __restrict__ ohT,
                               const float* __restrict__ resid, const float* __restrict__ gamma_p,
                               float* __restrict__ dst) {
    __shared__ float tile[32][33];
    int h0 = blockIdx.x * 32, w0 = blockIdx.y * 32;
    long base = (long)blockIdx.z * 9216;
    int tx = threadIdx.x, ty = threadIdx.y;
    float g = *gamma_p;
    #pragma unroll
    for (int k = 0; k < 4; k++)
        tile[ty + 8*k][tx] = ohT[base + (long)(w0 + ty + 8*k) * 96 + h0 + tx];
    __syncthreads();
    #pragma unroll
    for (int k = 0; k < 4; k++) {
        long idx = base + (long)(h0 + ty + 8*k) * 96 + w0 + tx;
        dst[idx] = g * (ow[idx] + tile[tx][ty + 8*k]) + resid[idx];
    }
}

// ---------------- batchnorm ----------------
__global__ void bn_stats_kernel(const float* __restrict__ x,
                                float* __restrict__ mean, float* __restrict__ rstd) {
    int c = blockIdx.x;
    float s = 0.0f, sq = 0.0f;
    for (int n = threadIdx.x; n < 8 * 9216; n += 256) {
        int b = n / 9216, i = n - b * 9216;
        float vv = x[((long)(b * 512 + c)) * 9216 + i];
        s += vv; sq += vv * vv;
    }
    __shared__ float sh1[256], sh2[256];
    sh1[threadIdx.x] = s; sh2[threadIdx.x] = sq;
    __syncthreads();
    for (int o = 128; o > 0; o >>= 1) {
        if (threadIdx.x < o) {
            sh1[threadIdx.x] += sh1[threadIdx.x + o];
            sh2[threadIdx.x] += sh2[threadIdx.x + o];
        }
        __syncthreads();
    }
    if (threadIdx.x == 0) {
        float m = sh1[0] / 73728.0f;
        float var = sh2[0] / 73728.0f - m * m;
        mean[c] = m;
        rstd[c] = rsqrtf(var + 1e-5f);
    }
}

__global__ void bn_apply_kernel(float4* __restrict__ x,
                                const float* __restrict__ mean, const float* __restrict__ rstd,
                                const float* __restrict__ scale, const float* __restrict__ bias) {
    long total = 8L * 512 * 2304;    // float4 count
    for (long idx = (long)blockIdx.x * blockDim.x + threadIdx.x; idx < total;
         idx += (long)gridDim.x * blockDim.x) {
        int c = (int)((idx / 2304) % 512);
        float mu = mean[c], rs = rstd[c], sc = scale[c], bi = bias[c];
        float4 v = x[idx];
        v.x = fmaxf((v.x - mu) * rs * sc + bi, 0.0f);
        v.y = fmaxf((v.y - mu) * rs * sc + bi, 0.0f);
        v.z = fmaxf((v.z - mu) * rs * sc + bi, 0.0f);
        v.w = fmaxf((v.w - mu) * rs * sc + bi, 0.0f);
        x[idx] = v;
    }
}

// ---------------- host ----------------
static inline void launch_gemm(const float* A, int lda, const float* Bm, long long bs,
                               const float* bias, float* Cm, long long cs,
                               int M, int K, int N, int acc) {
    dim3 grid(N / 128, (M + 127) / 128, 8);
    mma_gemm_kernel<<<grid, 256, GEMM_SMEM>>>(A, lda, Bm, bs, bias, Cm, cs, M, K, N, acc);
}

extern "C" void kernel_launch(void* const* d_in, const int* in_sizes, int n_in,
                              void* d_out, int out_size) {
    const float* low      = (const float*)d_in[0];
    const float* high     = (const float*)d_in[1];
    const float* conv1_w  = (const float*)d_in[2];
    const float* conv1_b  = (const float*)d_in[3];
    const float* conv2_w  = (const float*)d_in[4];
    const float* conv2_b  = (const float*)d_in[5];
    const float* q_w      = (const float*)d_in[6];
    const float* q_b      = (const float*)d_in[7];
    const float* k_w      = (const float*)d_in[8];
    const float* k_b      = (const float*)d_in[9];
    const float* v_w      = (const float*)d_in[10];
    const float* v_b      = (const float*)d_in[11];
    const float* gamma    = (const float*)d_in[12];
    const float* bw       = (const float*)d_in[13];
    const float* bn_scale = (const float*)d_in[14];
    const float* bn_bias  = (const float*)d_in[15];
    float* out = (float*)d_out;

    float *hf, *qf, *vf, *vf2, *qb, *kb, *vb, *qt, *kt, *vt;
    float *attH, *attW, *ohb, *owb, *meanp, *rstdp;
    cudaGetSymbolAddress((void**)&hf,   g_hf);
    cudaGetSymbolAddress((void**)&qf,   g_qf);
    cudaGetSymbolAddress((void**)&vf,   g_vf);
    cudaGetSymbolAddress((void**)&vf2,  g_vf2);
    cudaGetSymbolAddress((void**)&qb,   g_q);
    cudaGetSymbolAddress((void**)&kb,   g_k);
    cudaGetSymbolAddress((void**)&vb,   g_v);
    cudaGetSymbolAddress((void**)&qt,   g_qt);
    cudaGetSymbolAddress((void**)&kt,   g_kt);
    cudaGetSymbolAddress((void**)&vt,   g_vt);
    cudaGetSymbolAddress((void**)&attH, g_attH);
    cudaGetSymbolAddress((void**)&attW, g_attW);
    cudaGetSymbolAddress((void**)&ohb,  g_oh);
    cudaGetSymbolAddress((void**)&owb,  g_ow);
    cudaGetSymbolAddress((void**)&meanp, g_mean);
    cudaGetSymbolAddress((void**)&rstdp, g_rstd);

    cudaFuncSetAttribute(mma_gemm_kernel, cudaFuncAttributeMaxDynamicSharedMemorySize, GEMM_SMEM);
    cudaFuncSetAttribute(pv_mma_kernel,   cudaFuncAttributeMaxDynamicSharedMemorySize, PV_SMEM);

    // 1. upsample
    resize_kernel<<<4096, 256>>>(high, hf);

    // 2. projections
    launch_gemm(conv1_w, 512, low, 512LL * 9216, conv1_b, qf, 256LL * 9216, 256, 512, 9216, 0);
    launch_gemm(conv2_w, 512, hf, 512LL * 9216, conv2_b, vf, 256LL * 9216, 256, 512, 9216, 0);
    launch_gemm(q_w, 256, qf, 256LL * 9216, q_b, qb, 32LL * 9216, 32, 256, 9216, 0);
    transpose96_kernel<<<dim3(3, 3, 8 * 32), dim3(32, 8)>>>(qb, qt);

    for (int it = 0; it < 2; it++) {
        const float* src = it ? vf2 : vf;
        float* dstp      = it ? vf  : vf2;
        launch_gemm(k_w, 256, src, 256LL * 9216, k_b, kb, 32LL * 9216, 32, 256, 9216, 0);
        launch_gemm(v_w, 256, src, 256LL * 9216, v_b, vb, 256LL * 9216, 256, 256, 9216, 0);
        transpose96_kernel<<<dim3(3, 3, 8 * 32),  dim3(32, 8)>>>(kb, kt);
        transpose96_kernel<<<dim3(3, 3, 8 * 256), dim3(32, 8)>>>(vb, vt);
        qk_kernel<<<dim3(96, 8), 256>>>(qt, kt, attH, 1);   // eH (diag mask)
        qk_kernel<<<dim3(96, 8), 256>>>(qb, kb, attW, 0);   // eW
        softmax2_kernel<<<9216, dim3(32, 8)>>>(attH, attW);
        pv_mma_kernel<<<dim3(96, 8), 256, PV_SMEM>>>(vt, attH, ohb);   // -> ohT [b][c][w][h]
        pv_mma_kernel<<<dim3(96, 8), 256, PV_SMEM>>>(vb, attW, owb);   // -> ow  [b][c][h][w]
        combine_kernel<<<dim3(3, 3, 8 * 256), dim3(32, 8)>>>(owb, ohb, src, gamma, dstp);
    }

    // bottleneck
    launch_gemm(bw,       768, vf, 256LL * 9216, nullptr, out, 512LL * 9216, 512, 256, 9216, 0);
    launch_gemm(bw + 256, 768, hf, 512LL * 9216, nullptr, out, 512LL * 9216, 512, 512, 9216, 1);

    // batchnorm + relu
    bn_stats_kernel<<<512, 256>>>(out, meanp, rstdp);
    bn_apply_kernel<<<4608, 256>>>((float4*)out, meanp, rstdp, bn_scale, bn_bias);
}

// round 6
// speedup vs baseline: 2.7644x; 1.5044x over previous
#include <cuda_runtime.h>
#include <cuda_bf16.h>
#include <cstdint>

// ---------------- problem constants ----------------
#define NB   8
#define NC   512
#define NH   96
#define NW   96
#define NEG_INF_F (-1000000000.0f)

// ---------------- scratch ----------------
__device__ float g_hf [8L*512*96*96];
__device__ float g_qf [8L*256*96*96];
__device__ float g_vf [8L*256*96*96];
__device__ float g_vf2[8L*256*96*96];
__device__ float g_q  [8L*32*96*96];
__device__ float g_k  [8L*32*96*96];
__device__ float g_v  [8L*256*96*96];
__device__ float g_qt [8L*32*96*96];
__device__ float g_kt [8L*32*96*96];
__device__ float g_vt [8L*256*96*96];
__device__ float g_attH[8L*96*96*96];
__device__ float g_attW[8L*96*96*96];
__device__ float g_oh [8L*256*96*96];   // ohT: [b][c][w][h]
__device__ float g_ow [8L*256*96*96];   // ow : [b][c][h][w]
__device__ float g_mean[512];
__device__ float g_rstd[512];

// ---------------- bilinear 2x upsample ----------------
__global__ void resize_kernel(const float* __restrict__ in, float* __restrict__ out) {
    long total = (long)NB * NC * NH * NW;
    for (long idx = (long)blockIdx.x * blockDim.x + threadIdx.x; idx < total;
         idx += (long)gridDim.x * blockDim.x) {
        int ox = (int)(idx % NW);
        long t  = idx / NW;
        int oy = (int)(t % NH);
        long bc = t / NH;
        int my = oy >> 1, mx = ox >> 1;
        int y0, y1, x0, x1; float wy0, wx0;
        if (oy & 1) { y0 = my;                 y1 = (my < 47) ? my + 1 : 47; wy0 = 0.75f; }
        else        { y0 = (my > 0) ? my - 1 : 0; y1 = my;                   wy0 = 0.25f; }
        if (ox & 1) { x0 = mx;                 x1 = (mx < 47) ? mx + 1 : 47; wx0 = 0.75f; }
        else        { x0 = (mx > 0) ? mx - 1 : 0; x1 = mx;                   wx0 = 0.25f; }
        const float* p = in + bc * (48 * 48);
        float v00 = p[y0*48 + x0], v01 = p[y0*48 + x1];
        float v10 = p[y1*48 + x0], v11 = p[y1*48 + x1];
        float top = wx0 * v00 + (1.0f - wx0) * v01;
        float bot = wx0 * v10 + (1.0f - wx0) * v11;
        out[idx] = wy0 * top + (1.0f - wy0) * bot;
    }
}

// ---------------- mma helpers ----------------
__device__ __forceinline__ void cp16(uint32_t dst, const void* src, int bytes_valid) {
    asm volatile("cp.async.cg.shared.global [%0], [%1], 16, %2;"
                 :: "r"(dst), "l"(src), "r"(bytes_valid));
}
__device__ __forceinline__ void mma_tf32(float* c, const uint32_t* a, uint32_t b0, uint32_t b1) {
    asm volatile("mma.sync.aligned.m16n8k8.row.col.f32.tf32.tf32.f32 "
                 "{%0,%1,%2,%3}, {%4,%5,%6,%7}, {%8,%9}, {%0,%1,%2,%3};"
                 : "+f"(c[0]), "+f"(c[1]), "+f"(c[2]), "+f"(c[3])
                 : "r"(a[0]), "r"(a[1]), "r"(a[2]), "r"(a[3]), "r"(b0), "r"(b1));
}

// ---------------- big TF32 GEMM: block 128x256x32, warp 64x64, 3-stage ----------------
// C[b](MxN) = A(MxK) * X[b](KxN) (+bias). X rows: rows [0,kSplit) from B1, rest from B2.
#define GAPITCH 36
#define GBPITCH 264
#define GA_STG (128*GAPITCH)    // 4608 floats
#define GB_STG (32*GBPITCH)     // 8448 floats
#define GEMM_SMEM (3*(GA_STG+GB_STG)*4)   // 156672 bytes

__global__ void __launch_bounds__(256, 1) mma_gemm_kernel(
    const float* __restrict__ A, int lda,
    const float* __restrict__ B1, long long b1Stride,
    const float* __restrict__ B2, long long b2Stride, int kSplit,
    const float* __restrict__ bias,
    float* __restrict__ Cm, long long cStride,
    int M, int K, int N)
{
    extern __shared__ float sm[];
    float* sA = sm;
    float* sB = sm + 3 * GA_STG;
    const uint32_t sA_u = (uint32_t)__cvta_generic_to_shared(sA);
    const uint32_t sB_u = (uint32_t)__cvta_generic_to_shared(sB);

    const int tid  = threadIdx.x;
    const int warp = tid >> 5, lane = tid & 31;
    const int g = lane >> 2, tq = lane & 3;
    const int wm = (warp >> 2) * 64;        // {0,64}
    const int wn = (warp & 3) * 64;         // {0,64,128,192}
    const int m0 = blockIdx.y * 128;
    const int n0 = blockIdx.x * 256;
    const float* B1b = B1 + (long long)blockIdx.z * b1Stride;
    const float* B2b = B2 ? (B2 + (long long)blockIdx.z * b2Stride) : B1b;
    float* Cb        = Cm + (long long)blockIdx.z * cStride;

    // A: 4 x cp16 per chunk. B: 8 x cp16 per chunk.
    int arow[4], ac16[4], abytes[4];
    const float* aSrc[4];
    #pragma unroll
    for (int i = 0; i < 4; i++) {
        int ch = tid + 256 * i;
        arow[i] = ch >> 3;  ac16[i] = ch & 7;
        abytes[i] = (m0 + arow[i] < M) ? 16 : 0;
        aSrc[i] = A + (long long)(m0 + arow[i]) * lda + ac16[i] * 4;
    }
    int brow[8], bnoff[8], bdst[8];
    #pragma unroll
    for (int i = 0; i < 8; i++) {
        int ch = tid + 256 * i;
        brow[i] = ch >> 6;                  // 0..31
        int c16 = ch & 63;
        bnoff[i] = n0 + c16 * 4;
        bdst[i] = (brow[i] * GBPITCH + c16 * 4) * 4;
    }

    const int nch = K >> 5;

    #pragma unroll
    for (int c = 0; c < 2; c++) {
        int kc = c * 32;
        uint32_t da = sA_u + (c * GA_STG) * 4;
        uint32_t db = sB_u + (c * GB_STG) * 4;
        #pragma unroll
        for (int i = 0; i < 4; i++)
            cp16(da + (arow[i] * GAPITCH + ac16[i] * 4) * 4, aSrc[i] + kc, abytes[i]);
        #pragma unroll
        for (int i = 0; i < 8; i++) {
            int row = kc + brow[i];
            const float* src = (row < kSplit) ? (B1b + (long long)row * N + bnoff[i])
                                              : (B2b + (long long)(row - kSplit) * N + bnoff[i]);
            cp16(db + bdst[i], src, 16);
        }
        asm volatile("cp.async.commit_group;");
    }

    float acc[4][8][4];
    #pragma unroll
    for (int mf = 0; mf < 4; mf++)
        #pragma unroll
        for (int nf = 0; nf < 8; nf++)
            #pragma unroll
            for (int i = 0; i < 4; i++) acc[mf][nf][i] = 0.0f;

    for (int c = 0; c < nch; c++) {
        if (c + 1 < nch) asm volatile("cp.async.wait_group 1;");
        else             asm volatile("cp.async.wait_group 0;");
        __syncthreads();

        if (c + 2 < nch) {
            int s = (c + 2) % 3;
            int kc = (c + 2) * 32;
            uint32_t da = sA_u + (s * GA_STG) * 4;
            uint32_t db = sB_u + (s * GB_STG) * 4;
            #pragma unroll
            for (int i = 0; i < 4; i++)
                cp16(da + (arow[i] * GAPITCH + ac16[i] * 4) * 4, aSrc[i] + kc, abytes[i]);
            #pragma unroll
            for (int i = 0; i < 8; i++) {
                int row = kc + brow[i];
                const float* src = (row < kSplit) ? (B1b + (long long)row * N + bnoff[i])
                                                  : (B2b + (long long)(row - kSplit) * N + bnoff[i]);
                cp16(db + bdst[i], src, 16);
            }
            asm volatile("cp.async.commit_group;");
        }

        const float* As_ = sA + (c % 3) * GA_STG;
        const float* Bs_ = sB + (c % 3) * GB_STG;
        #pragma unroll
        for (int ks = 0; ks < 4; ks++) {
            const int k1 = ks * 8 + tq, k2 = k1 + 4;
            uint32_t afr[4][4];
            #pragma unroll
            for (int mf = 0; mf < 4; mf++) {
                int mb = wm + mf * 16 + g;
                afr[mf][0] = __float_as_uint(As_[mb * GAPITCH + k1]);
                afr[mf][1] = __float_as_uint(As_[(mb + 8) * GAPITCH + k1]);
                afr[mf][2] = __float_as_uint(As_[mb * GAPITCH + k2]);
                afr[mf][3] = __float_as_uint(As_[(mb + 8) * GAPITCH + k2]);
            }
            #pragma unroll
            for (int nf = 0; nf < 8; nf++) {
                int nb = wn + nf * 8 + g;
                uint32_t b0 = __float_as_uint(Bs_[k1 * GBPITCH + nb]);
                uint32_t b1 = __float_as_uint(Bs_[k2 * GBPITCH + nb]);
                #pragma unroll
                for (int mf = 0; mf < 4; mf++)
                    mma_tf32(acc[mf][nf], afr[mf], b0, b1);
            }
        }
    }

    #pragma unroll
    for (int mf = 0; mf < 4; mf++) {
        #pragma unroll
        for (int half = 0; half < 2; half++) {
            int r = m0 + wm + mf * 16 + g + half * 8;
            if (r < M) {
                float bia = bias ? bias[r] : 0.0f;
                float* crow = Cb + (long long)r * N;
                #pragma unroll
                for (int nf = 0; nf < 8; nf++) {
                    int cc = n0 + wn + nf * 8 + 2 * tq;
                    float2 cv;
                    cv.x = acc[mf][nf][half * 2 + 0] + bia;
                    cv.y = acc[mf][nf][half * 2 + 1] + bia;
                    *(float2*)(crow + cc) = cv;
                }
            }
        }
    }
}

// ---------------- small-M (M=32) TF32 GEMM: block 32x256x32, warp 32x32, 2-stage ----------------
#define SA_STG (32*GAPITCH)     // 1152 floats
#define SB_STG (32*GBPITCH)     // 8448 floats
#define GEMM32_SMEM (2*(SA_STG+SB_STG)*4)   // 76800 bytes

__global__ void __launch_bounds__(256, 2) mma_gemm32_kernel(
    const float* __restrict__ A, int lda,
    const float* __restrict__ Bm, long long bStride,
    const float* __restrict__ bias,
    float* __restrict__ Cm, long long cStride,
    int K, int N)
{
    extern __shared__ float sm[];
    float* sA = sm;
    float* sB = sm + 2 * SA_STG;
    const uint32_t sA_u = (uint32_t)__cvta_generic_to_shared(sA);
    const uint32_t sB_u = (uint32_t)__cvta_generic_to_shared(sB);

    const int tid  = threadIdx.x;
    const int warp = tid >> 5, lane = tid & 31;
    const int g = lane >> 2, tq = lane & 3;
    const int wn = warp * 32;
    const int n0 = blockIdx.x * 256;
    const float* Bb = Bm + (long long)blockIdx.z * bStride;
    float* Cb       = Cm + (long long)blockIdx.z * cStride;

    const int ar = tid >> 3, ac16 = tid & 7;
    const float* aSrc = A + (long long)ar * lda + ac16 * 4;
    const uint32_t adst = (ar * GAPITCH + ac16 * 4) * 4;

    int brow[8], bdst[8];
    const float* bSrc[8];
    #pragma unroll
    for (int i = 0; i < 8; i++) {
        int ch = tid + 256 * i;
        brow[i] = ch >> 6;
        int c16 = ch & 63;
        bdst[i] = (brow[i] * GBPITCH + c16 * 4) * 4;
        bSrc[i] = Bb + (long long)brow[i] * N + n0 + c16 * 4;
    }

    const int nch = K >> 5;

    // prologue: chunk 0
    cp16(sA_u + adst, aSrc, 16);
    #pragma unroll
    for (int i = 0; i < 8; i++) cp16(sB_u + bdst[i], bSrc[i], 16);
    asm volatile("cp.async.commit_group;");

    float acc[2][4][4];
    #pragma unroll
    for (int mf = 0; mf < 2; mf++)
        #pragma unroll
        for (int nf = 0; nf < 4; nf++)
            #pragma unroll
            for (int i = 0; i < 4; i++) acc[mf][nf][i] = 0.0f;

    for (int c = 0; c < nch; c++) {
        if (c + 1 < nch) {
            int s = (c + 1) & 1;
            int kc = (c + 1) * 32;
            uint32_t da = sA_u + (s * SA_STG) * 4;
            uint32_t db = sB_u + (s * SB_STG) * 4;
            cp16(da + adst, aSrc + kc, 16);
            #pragma unroll
            for (int i = 0; i < 8; i++)
                cp16(db + bdst[i], bSrc[i] + (long long)kc * N, 16);
            asm volatile("cp.async.commit_group;");
            asm volatile("cp.async.wait_group 1;");
        } else {
            asm volatile("cp.async.wait_group 0;");
        }
        __syncthreads();

        const float* As_ = sA + (c & 1) * SA_STG;
        const float* Bs_ = sB + (c & 1) * SB_STG;
        #pragma unroll
        for (int ks = 0; ks < 4; ks++) {
            const int k1 = ks * 8 + tq, k2 = k1 + 4;
            uint32_t afr[2][4];
            #pragma unroll
            for (int mf = 0; mf < 2; mf++) {
                int mb = mf * 16 + g;
                afr[mf][0] = __float_as_uint(As_[mb * GAPITCH + k1]);
                afr[mf][1] = __float_as_uint(As_[(mb + 8) * GAPITCH + k1]);
                afr[mf][2] = __float_as_uint(As_[mb * GAPITCH + k2]);
                afr[mf][3] = __float_as_uint(As_[(mb + 8) * GAPITCH + k2]);
            }
            #pragma unroll
            for (int nf = 0; nf < 4; nf++) {
                int nb = wn + nf * 8 + g;
                uint32_t b0 = __float_as_uint(Bs_[k1 * GBPITCH + nb]);
                uint32_t b1 = __float_as_uint(Bs_[k2 * GBPITCH + nb]);
                #pragma unroll
                for (int mf = 0; mf < 2; mf++)
                    mma_tf32(acc[mf][nf], afr[mf], b0, b1);
            }
        }
        __syncthreads();
    }

    #pragma unroll
    for (int mf = 0; mf < 2; mf++) {
        #pragma unroll
        for (int half = 0; half < 2; half++) {
            int r = mf * 16 + g + half * 8;
            float bia = bias ? bias[r] : 0.0f;
            float* crow = Cb + (long long)r * N;
            #pragma unroll
            for (int nf = 0; nf < 4; nf++) {
                int cc = n0 + wn + nf * 8 + 2 * tq;
                float2 cv;
                cv.x = acc[mf][nf][half * 2 + 0] + bia;
                cv.y = acc[mf][nf][half * 2 + 1] + bia;
                *(float2*)(crow + cc) = cv;
            }
        }
    }
}

// ---------------- tiled 96x96 plane transpose ----------------
__global__ void transpose96_kernel(const float* __restrict__ in, float* __restrict__ out) {
    __shared__ float tile[32][33];
    int x0 = blockIdx.x * 32, y0 = blockIdx.y * 32;
    long base = (long)blockIdx.z * 9216;
    int tx = threadIdx.x, ty = threadIdx.y;
    #pragma unroll
    for (int k = 0; k < 4; k++)
        tile[ty + 8*k][tx] = in[base + (long)(y0 + ty + 8*k) * 96 + x0 + tx];
    __syncthreads();
    #pragma unroll
    for (int k = 0; k < 4; k++)
        out[base + (long)(x0 + ty + 8*k) * 96 + y0 + tx] = tile[tx][ty + 8*k];
}

// ---------------- qk logits ----------------
__global__ void __launch_bounds__(256) qk_kernel(const float* __restrict__ qsrc,
                                                 const float* __restrict__ ksrc,
                                                 float* __restrict__ attX, int diag) {
    int x = blockIdx.x, b = blockIdx.y;
    __shared__ float Qs[32][97], Ks[32][97];
    int tid = threadIdx.x;
    for (int idx = tid; idx < 3072; idx += 256) {
        int ci = idx / 96, inner = idx % 96;
        long off = ((long)((b * 32 + ci) * 96 + x)) * 96 + inner;
        Qs[ci][inner] = qsrc[off];
        Ks[ci][inner] = ksrc[off];
    }
    __syncthreads();
    float* ab = attX + ((long)(b * 96 + x)) * 9216;
    for (int idx = tid; idx < 2304; idx += 256) {
        int o = idx / 24;
        int P0 = (idx % 24) * 4;
        float acc[4];
        #pragma unroll
        for (int j = 0; j < 4; j++) acc[j] = (diag && (P0 + j == o)) ? NEG_INF_F : 0.0f;
        #pragma unroll
        for (int c = 0; c < 32; c++) {
            float qv = Qs[c][o];
            #pragma unroll
            for (int j = 0; j < 4; j++) acc[j] += qv * Ks[c][P0 + j];
        }
        *(float4*)(ab + o * 96 + P0) = make_float4(acc[0], acc[1], acc[2], acc[3]);
    }
}

// ---------------- joint softmax ----------------
__global__ void softmax2_kernel(float* __restrict__ attH, float* __restrict__ attW) {
    int row = blockIdx.x * 8 + threadIdx.y;
    int b = row / 9216, rem = row % 9216, h = rem / 96, w = rem % 96;
    float* pH = attH + ((long)(b * 96 + w) * 96 + h) * 96;
    float* pW = attW + ((long)(b * 96 + h) * 96 + w) * 96;
    int lane = threadIdx.x;
    float v[6];
    #pragma unroll
    for (int j = 0; j < 3; j++) v[j]     = pH[j * 32 + lane];
    #pragma unroll
    for (int j = 0; j < 3; j++) v[3 + j] = pW[j * 32 + lane];
    float m = -3.0e38f;
    #pragma unroll
    for (int j = 0; j < 6; j++) m = fmaxf(m, v[j]);
    #pragma unroll
    for (int o = 16; o > 0; o >>= 1) m = fmaxf(m, __shfl_xor_sync(0xffffffffu, m, o));
    float s = 0.0f;
    #pragma unroll
    for (int j = 0; j < 6; j++) { v[j] = expf(v[j] - m); s += v[j]; }
    #pragma unroll
    for (int o = 16; o > 0; o >>= 1) s += __shfl_xor_sync(0xffffffffu, s, o);
    float inv = 1.0f / s;
    #pragma unroll
    for (int j = 0; j < 3; j++) pH[j * 32 + lane] = v[j] * inv;
    #pragma unroll
    for (int j = 0; j < 3; j++) pW[j * 32 + lane] = v[3 + j] * inv;
}

// ---------------- P*V via tensor cores ----------------
#define PV_SMEM ((96*100 + 128*100) * 4)
__global__ void __launch_bounds__(256) pv_mma_kernel(const float* __restrict__ Vsrc,
                                                     const float* __restrict__ attX,
                                                     float* __restrict__ outX) {
    extern __shared__ float sh[];
    float* Ah = sh;              // [96][100]
    float* Vs = sh + 96 * 100;   // [128][100]
    int x = blockIdx.x, b = blockIdx.y;
    int tid = threadIdx.x;
    int warp = tid >> 5, lane = tid & 31;
    int g = lane >> 2, tq = lane & 3;
    int wm = (warp >> 2) * 64;
    int wn = (warp & 3) * 24;

    const float* ab = attX + ((long)(b * 96 + x)) * 9216;
    for (int i4 = tid; i4 < 96 * 24; i4 += 256) {
        int h = i4 / 24, f = i4 % 24;
        float4 v4 = *(const float4*)(ab + i4 * 4);
        *(float4*)&Ah[h * 100 + f * 4] = v4;
    }

    #pragma unroll
    for (int half = 0; half < 2; half++) {
        const float* vb = Vsrc + (((long)(b * 256 + half * 128)) * 96 + x) * 96;
        for (int i4 = tid; i4 < 128 * 24; i4 += 256) {
            int ci = i4 / 24, f = i4 % 24;
            float4 v4 = *(const float4*)(vb + (long)ci * 9216 + f * 4);
            *(float4*)&Vs[ci * 100 + f * 4] = v4;
        }
        __syncthreads();

        float acc[4][3][4];
        #pragma unroll
        for (int mf = 0; mf < 4; mf++)
            #pragma unroll
            for (int nf = 0; nf < 3; nf++)
                #pragma unroll
                for (int i = 0; i < 4; i++) acc[mf][nf][i] = 0.0f;

        #pragma unroll
        for (int ks = 0; ks < 12; ks++) {
            int k1 = ks * 8 + tq, k2 = k1 + 4;
            uint32_t afr[4][4];
            #pragma unroll
            for (int mf = 0; mf < 4; mf++) {
                int mb = wm + mf * 16 + g;
                afr[mf][0] = __float_as_uint(Vs[mb * 100 + k1]);
                afr[mf][1] = __float_as_uint(Vs[(mb + 8) * 100 + k1]);
                afr[mf][2] = __float_as_uint(Vs[mb * 100 + k2]);
                afr[mf][3] = __float_as_uint(Vs[(mb + 8) * 100 + k2]);
            }
            #pragma unroll
            for (int nf = 0; nf < 3; nf++) {
                int nb = wn + nf * 8 + g;
                uint32_t b0 = __float_as_uint(Ah[nb * 100 + k1]);
                uint32_t b1 = __float_as_uint(Ah[nb * 100 + k2]);
                #pragma unroll
                for (int mf = 0; mf < 4; mf++)
                    mma_tf32(acc[mf][nf], afr[mf], b0, b1);
            }
        }
        __syncthreads();

        #pragma unroll
        for (int mf = 0; mf < 4; mf++) {
            #pragma unroll
            for (int hm = 0; hm < 2; hm++) {
                int c = half * 128 + wm + mf * 16 + g + hm * 8;
                float* orow = outX + (((long)(b * 256 + c)) * 96 + x) * 96;
                #pragma unroll
                for (int nf = 0; nf < 3; nf++) {
                    int col = wn + nf * 8 + 2 * tq;
                    float2 cv;
                    cv.x = acc[mf][nf][hm * 2 + 0];
                    cv.y = acc[mf][nf][hm * 2 + 1];
                    *(float2*)(orow + col) = cv;
                }
            }
        }
    }
}

// ---------------- combine ----------------
__global__ void combine_kernel(const float* __restrict__ ow, const float* __restrict__ ohT,
                               const float* __restrict__ resid, const float* __restrict__ gamma_p,
                               float* __restrict__ dst) {
    __shared__ float tile[32][33];
    int h0 = blockIdx.x * 32, w0 = blockIdx.y * 32;
    long base = (long)blockIdx.z * 9216;
    int tx = threadIdx.x, ty = threadIdx.y;
    float g = *gamma_p;
    #pragma unroll
    for (int k = 0; k < 4; k++)
        tile[ty + 8*k][tx] = ohT[base + (long)(w0 + ty + 8*k) * 96 + h0 + tx];
    __syncthreads();
    #pragma unroll
    for (int k = 0; k < 4; k++) {
        long idx = base + (long)(h0 + ty + 8*k) * 96 + w0 + tx;
        dst[idx] = g * (ow[idx] + tile[tx][ty + 8*k]) + resid[idx];
    }
}

// ---------------- batchnorm ----------------
__global__ void bn_stats_kernel(const float* __restrict__ x,
                                float* __restrict__ mean, float* __restrict__ rstd) {
    int c = blockIdx.x;
    float s = 0.0f, sq = 0.0f;
    for (int n = threadIdx.x; n < 8 * 9216; n += 256) {
        int b = n / 9216, i = n - b * 9216;
        float vv = x[((long)(b * 512 + c)) * 9216 + i];
        s += vv; sq += vv * vv;
    }
    __shared__ float sh1[256], sh2[256];
    sh1[threadIdx.x] = s; sh2[threadIdx.x] = sq;
    __syncthreads();
    for (int o = 128; o > 0; o >>= 1) {
        if (threadIdx.x < o) {
            sh1[threadIdx.x] += sh1[threadIdx.x + o];
            sh2[threadIdx.x] += sh2[threadIdx.x + o];
        }
        __syncthreads();
    }
    if (threadIdx.x == 0) {
        float m = sh1[0] / 73728.0f;
        float var = sh2[0] / 73728.0f - m * m;
        mean[c] = m;
        rstd[c] = rsqrtf(var + 1e-5f);
    }
}

__global__ void bn_apply_kernel(float4* __restrict__ x,
                                const float* __restrict__ mean, const float* __restrict__ rstd,
                                const float* __restrict__ scale, const float* __restrict__ bias) {
    long total = 8L * 512 * 2304;
    for (long idx = (long)blockIdx.x * blockDim.x + threadIdx.x; idx < total;
         idx += (long)gridDim.x * blockDim.x) {
        int c = (int)((idx / 2304) % 512);
        float mu = mean[c], rs = rstd[c], sc = scale[c], bi = bias[c];
        float4 v = x[idx];
        v.x = fmaxf((v.x - mu) * rs * sc + bi, 0.0f);
        v.y = fmaxf((v.y - mu) * rs * sc + bi, 0.0f);
        v.z = fmaxf((v.z - mu) * rs * sc + bi, 0.0f);
        v.w = fmaxf((v.w - mu) * rs * sc + bi, 0.0f);
        x[idx] = v;
    }
}

// ---------------- host ----------------
static inline void launch_gemm(const float* A, int lda, const float* Bm, long long bs,
                               const float* bias, float* Cm, long long cs,
                               int M, int K, int N) {
    dim3 grid(N / 256, (M + 127) / 128, 8);
    mma_gemm_kernel<<<grid, 256, GEMM_SMEM>>>(A, lda, Bm, bs, nullptr, 0, 1 << 30,
                                              bias, Cm, cs, M, K, N);
}

extern "C" void kernel_launch(void* const* d_in, const int* in_sizes, int n_in,
                              void* d_out, int out_size) {
    const float* low      = (const float*)d_in[0];
    const float* high     = (const float*)d_in[1];
    const float* conv1_w  = (const float*)d_in[2];
    const float* conv1_b  = (const float*)d_in[3];
    const float* conv2_w  = (const float*)d_in[4];
    const float* conv2_b  = (const float*)d_in[5];
    const float* q_w      = (const float*)d_in[6];
    const float* q_b      = (const float*)d_in[7];
    const float* k_w      = (const float*)d_in[8];
    const float* k_b      = (const float*)d_in[9];
    const float* v_w      = (const float*)d_in[10];
    const float* v_b      = (const float*)d_in[11];
    const float* gamma    = (const float*)d_in[12];
    const float* bw       = (const float*)d_in[13];
    const float* bn_scale = (const float*)d_in[14];
    const float* bn_bias  = (const float*)d_in[15];
    float* out = (float*)d_out;

    float *hf, *qf, *vf, *vf2, *qb, *kb, *vb, *qt, *kt, *vt;
    float *attH, *attW, *ohb, *owb, *meanp, *rstdp;
    cudaGetSymbolAddress((void**)&hf,   g_hf);
    cudaGetSymbolAddress((void**)&qf,   g_qf);
    cudaGetSymbolAddress((void**)&vf,   g_vf);
    cudaGetSymbolAddress((void**)&vf2,  g_vf2);
    cudaGetSymbolAddress((void**)&qb,   g_q);
    cudaGetSymbolAddress((void**)&kb,   g_k);
    cudaGetSymbolAddress((void**)&vb,   g_v);
    cudaGetSymbolAddress((void**)&qt,   g_qt);
    cudaGetSymbolAddress((void**)&kt,   g_kt);
    cudaGetSymbolAddress((void**)&vt,   g_vt);
    cudaGetSymbolAddress((void**)&attH, g_attH);
    cudaGetSymbolAddress((void**)&attW, g_attW);
    cudaGetSymbolAddress((void**)&ohb,  g_oh);
    cudaGetSymbolAddress((void**)&owb,  g_ow);
    cudaGetSymbolAddress((void**)&meanp, g_mean);
    cudaGetSymbolAddress((void**)&rstdp, g_rstd);

    cudaFuncSetAttribute(mma_gemm_kernel,   cudaFuncAttributeMaxDynamicSharedMemorySize, GEMM_SMEM);
    cudaFuncSetAttribute(mma_gemm32_kernel, cudaFuncAttributeMaxDynamicSharedMemorySize, GEMM32_SMEM);
    cudaFuncSetAttribute(pv_mma_kernel,     cudaFuncAttributeMaxDynamicSharedMemorySize, PV_SMEM);

    // 1. upsample
    resize_kernel<<<4096, 256>>>(high, hf);

    // 2. projections
    launch_gemm(conv1_w, 512, low, 512LL * 9216, conv1_b, qf, 256LL * 9216, 256, 512, 9216);
    launch_gemm(conv2_w, 512, hf, 512LL * 9216, conv2_b, vf, 256LL * 9216, 256, 512, 9216);
    mma_gemm32_kernel<<<dim3(36, 1, 8), 256, GEMM32_SMEM>>>(
        q_w, 256, qf, 256LL * 9216, q_b, qb, 32LL * 9216, 256, 9216);
    transpose96_kernel<<<dim3(3, 3, 8 * 32), dim3(32, 8)>>>(qb, qt);

    for (int it = 0; it < 2; it++) {
        const float* src = it ? vf2 : vf;
        float* dstp      = it ? vf  : vf2;
        mma_gemm32_kernel<<<dim3(36, 1, 8), 256, GEMM32_SMEM>>>(
            k_w, 256, src, 256LL * 9216, k_b, kb, 32LL * 9216, 256, 9216);
        launch_gemm(v_w, 256, src, 256LL * 9216, v_b, vb, 256LL * 9216, 256, 256, 9216);
        transpose96_kernel<<<dim3(3, 3, 8 * 32),  dim3(32, 8)>>>(kb, kt);
        transpose96_kernel<<<dim3(3, 3, 8 * 256), dim3(32, 8)>>>(vb, vt);
        qk_kernel<<<dim3(96, 8), 256>>>(qt, kt, attH, 1);
        qk_kernel<<<dim3(96, 8), 256>>>(qb, kb, attW, 0);
        softmax2_kernel<<<9216, dim3(32, 8)>>>(attH, attW);
        pv_mma_kernel<<<dim3(96, 8), 256, PV_SMEM>>>(vt, attH, ohb);
        pv_mma_kernel<<<dim3(96, 8), 256, PV_SMEM>>>(vb, attW, owb);
        combine_kernel<<<dim3(3, 3, 8 * 256), dim3(32, 8)>>>(owb, ohb, src, gamma, dstp);
    }

    // bottleneck: single K=768 pass, B rows [0,256) from vf, [256,768) from hf
    {
        dim3 grid(9216 / 256, 512 / 128, 8);
        mma_gemm_kernel<<<grid, 256, GEMM_SMEM>>>(
            bw, 768, vf, 256LL * 9216, hf, 512LL * 9216, 256,
            nullptr, out, 512LL * 9216, 512, 768, 9216);
    }

    // batchnorm + relu
    bn_stats_kernel<<<512, 256>>>(out, meanp, rstdp);
    bn_apply_kernel<<<4608, 256>>>((float4*)out, meanp, rstdp, bn_scale, bn_bias);
}

// round 7
// speedup vs baseline: 3.0241x; 1.0939x over previous
#include <cuda_runtime.h>
#include <cuda_bf16.h>
#include <cstdint>

// ---------------- problem constants ----------------
#define NB   8
#define NC   512
#define NH   96
#define NW   96
#define NEG_INF_F (-1000000000.0f)

// ---------------- scratch ----------------
__device__ float g_hf [8L*512*96*96];
__device__ float g_qf [8L*256*96*96];
__device__ float g_vf [8L*256*96*96];
__device__ float g_vf2[8L*256*96*96];
__device__ float g_q  [8L*32*96*96];
__device__ float g_k  [8L*32*96*96];
__device__ float g_v  [8L*256*96*96];
__device__ float g_qt [8L*32*96*96];
__device__ float g_kt [8L*32*96*96];
__device__ float g_vt [8L*256*96*96];
__device__ float g_attH[8L*96*96*96];
__device__ float g_attW[8L*96*96*96];
__device__ float g_oh [8L*256*96*96];   // ohT: [b][c][w][h]
__device__ float g_ow [8L*256*96*96];   // ow : [b][c][h][w]
__device__ float g_stats[1024];         // [0:512) sum, [512:1024) sumsq

// ---------------- bilinear 2x upsample (float4) + stats zeroing ----------------
__global__ void resize_kernel(const float* __restrict__ in, float* __restrict__ out,
                              float* __restrict__ stats) {
    long gtid = (long)blockIdx.x * blockDim.x + threadIdx.x;
    if (gtid < 1024) stats[gtid] = 0.0f;
    long total4 = (long)NB * NC * NH * (NW / 4);
    for (long idx = gtid; idx < total4; idx += (long)gridDim.x * blockDim.x) {
        int ox0 = (int)(idx % 24) * 4;
        long t  = idx / 24;
        int oy = (int)(t % NH);
        long bc = t / NH;
        int my = oy >> 1;
        int y0, y1; float wy0;
        if (oy & 1) { y0 = my;                 y1 = (my < 47) ? my + 1 : 47; wy0 = 0.75f; }
        else        { y0 = (my > 0) ? my - 1 : 0; y1 = my;                   wy0 = 0.25f; }
        const float* p = in + bc * (48 * 48);
        float r[4];
        #pragma unroll
        for (int j = 0; j < 4; j++) {
            int ox = ox0 + j;
            int mx = ox >> 1;
            int x0, x1; float wx0;
            if (ox & 1) { x0 = mx;                 x1 = (mx < 47) ? mx + 1 : 47; wx0 = 0.75f; }
            else        { x0 = (mx > 0) ? mx - 1 : 0; x1 = mx;                   wx0 = 0.25f; }
            float v00 = p[y0*48 + x0], v01 = p[y0*48 + x1];
            float v10 = p[y1*48 + x0], v11 = p[y1*48 + x1];
            float top = wx0 * v00 + (1.0f - wx0) * v01;
            float bot = wx0 * v10 + (1.0f - wx0) * v11;
            r[j] = wy0 * top + (1.0f - wy0) * bot;
        }
        *(float4*)(out + idx * 4) = make_float4(r[0], r[1], r[2], r[3]);
    }
}

// ---------------- mma helpers ----------------
__device__ __forceinline__ void cp16(uint32_t dst, const void* src, int bytes_valid) {
    asm volatile("cp.async.cg.shared.global [%0], [%1], 16, %2;"
                 :: "r"(dst), "l"(src), "r"(bytes_valid));
}
__device__ __forceinline__ void mma_tf32(float* c, const uint32_t* a, uint32_t b0, uint32_t b1) {
    asm volatile("mma.sync.aligned.m16n8k8.row.col.f32.tf32.tf32.f32 "
                 "{%0,%1,%2,%3}, {%4,%5,%6,%7}, {%8,%9}, {%0,%1,%2,%3};"
                 : "+f"(c[0]), "+f"(c[1]), "+f"(c[2]), "+f"(c[3])
                 : "r"(a[0]), "r"(a[1]), "r"(a[2]), "r"(a[3]), "r"(b0), "r"(b1));
}

// ---------------- big TF32 GEMM: block 128x256x32, warp 64x64, 3-stage ----------------
#define GAPITCH 36
#define GBPITCH 264
#define GA_STG (128*GAPITCH)
#define GB_STG (32*GBPITCH)
#define GEMM_SMEM (3*(GA_STG+GB_STG)*4)   // 156672 bytes

__global__ void __launch_bounds__(256, 1) mma_gemm_kernel(
    const float* __restrict__ A, int lda,
    const float* __restrict__ B1, long long b1Stride,
    const float* __restrict__ B2, long long b2Stride, int kSplit,
    const float* __restrict__ bias,
    float* __restrict__ Cm, long long cStride,
    int M, int K, int N, float* __restrict__ stats)
{
    extern __shared__ float sm[];
    float* sA = sm;
    float* sB = sm + 3 * GA_STG;
    const uint32_t sA_u = (uint32_t)__cvta_generic_to_shared(sA);
    const uint32_t sB_u = (uint32_t)__cvta_generic_to_shared(sB);
    __shared__ float bnS[128], bnQ[128];

    const int tid  = threadIdx.x;
    if (tid < 128) { bnS[tid] = 0.0f; bnQ[tid] = 0.0f; }
    const int warp = tid >> 5, lane = tid & 31;
    const int g = lane >> 2, tq = lane & 3;
    const int wm = (warp >> 2) * 64;
    const int wn = (warp & 3) * 64;
    const int m0 = blockIdx.y * 128;
    const int n0 = blockIdx.x * 256;
    const float* B1b = B1 + (long long)blockIdx.z * b1Stride;
    const float* B2b = B2 ? (B2 + (long long)blockIdx.z * b2Stride) : B1b;
    float* Cb        = Cm + (long long)blockIdx.z * cStride;

    int arow[4], ac16[4], abytes[4];
    const float* aSrc[4];
    #pragma unroll
    for (int i = 0; i < 4; i++) {
        int ch = tid + 256 * i;
        arow[i] = ch >> 3;  ac16[i] = ch & 7;
        abytes[i] = (m0 + arow[i] < M) ? 16 : 0;
        aSrc[i] = A + (long long)(m0 + arow[i]) * lda + ac16[i] * 4;
    }
    int brow[8], bnoff[8], bdst[8];
    #pragma unroll
    for (int i = 0; i < 8; i++) {
        int ch = tid + 256 * i;
        brow[i] = ch >> 6;
        int c16 = ch & 63;
        bnoff[i] = n0 + c16 * 4;
        bdst[i] = (brow[i] * GBPITCH + c16 * 4) * 4;
    }

    const int nch = K >> 5;

    #pragma unroll
    for (int c = 0; c < 2; c++) {
        int kc = c * 32;
        uint32_t da = sA_u + (c * GA_STG) * 4;
        uint32_t db = sB_u + (c * GB_STG) * 4;
        #pragma unroll
        for (int i = 0; i < 4; i++)
            cp16(da + (arow[i] * GAPITCH + ac16[i] * 4) * 4, aSrc[i] + kc, abytes[i]);
        #pragma unroll
        for (int i = 0; i < 8; i++) {
            int row = kc + brow[i];
            const float* src = (row < kSplit) ? (B1b + (long long)row * N + bnoff[i])
                                              : (B2b + (long long)(row - kSplit) * N + bnoff[i]);
            cp16(db + bdst[i], src, 16);
        }
        asm volatile("cp.async.commit_group;");
    }

    float acc[4][8][4];
    #pragma unroll
    for (int mf = 0; mf < 4; mf++)
        #pragma unroll
        for (int nf = 0; nf < 8; nf++)
            #pragma unroll
            for (int i = 0; i < 4; i++) acc[mf][nf][i] = 0.0f;

    for (int c = 0; c < nch; c++) {
        if (c + 1 < nch) asm volatile("cp.async.wait_group 1;");
        else             asm volatile("cp.async.wait_group 0;");
        __syncthreads();

        if (c + 2 < nch) {
            int s = (c + 2) % 3;
            int kc = (c + 2) * 32;
            uint32_t da = sA_u + (s * GA_STG) * 4;
            uint32_t db = sB_u + (s * GB_STG) * 4;
            #pragma unroll
            for (int i = 0; i < 4; i++)
                cp16(da + (arow[i] * GAPITCH + ac16[i] * 4) * 4, aSrc[i] + kc, abytes[i]);
            #pragma unroll
            for (int i = 0; i < 8; i++) {
                int row = kc + brow[i];
                const float* src = (row < kSplit) ? (B1b + (long long)row * N + bnoff[i])
                                                  : (B2b + (long long)(row - kSplit) * N + bnoff[i]);
                cp16(db + bdst[i], src, 16);
            }
            asm volatile("cp.async.commit_group;");
        }

        const float* As_ = sA + (c % 3) * GA_STG;
        const float* Bs_ = sB + (c % 3) * GB_STG;
        #pragma unroll
        for (int ks = 0; ks < 4; ks++) {
            const int k1 = ks * 8 + tq, k2 = k1 + 4;
            uint32_t afr[4][4];
            #pragma unroll
            for (int mf = 0; mf < 4; mf++) {
                int mb = wm + mf * 16 + g;
                afr[mf][0] = __float_as_uint(As_[mb * GAPITCH + k1]);
                afr[mf][1] = __float_as_uint(As_[(mb + 8) * GAPITCH + k1]);
                afr[mf][2] = __float_as_uint(As_[mb * GAPITCH + k2]);
                afr[mf][3] = __float_as_uint(As_[(mb + 8) * GAPITCH + k2]);
            }
            #pragma unroll
            for (int nf = 0; nf < 8; nf++) {
                int nb = wn + nf * 8 + g;
                uint32_t b0 = __float_as_uint(Bs_[k1 * GBPITCH + nb]);
                uint32_t b1 = __float_as_uint(Bs_[k2 * GBPITCH + nb]);
                #pragma unroll
                for (int mf = 0; mf < 4; mf++)
                    mma_tf32(acc[mf][nf], afr[mf], b0, b1);
            }
        }
    }

    #pragma unroll
    for (int mf = 0; mf < 4; mf++) {
        #pragma unroll
        for (int half = 0; half < 2; half++) {
            int r = m0 + wm + mf * 16 + g + half * 8;
            if (r < M) {
                float bia = bias ? bias[r] : 0.0f;
                float* crow = Cb + (long long)r * N;
                float s = 0.0f, q = 0.0f;
                #pragma unroll
                for (int nf = 0; nf < 8; nf++) {
                    int cc = n0 + wn + nf * 8 + 2 * tq;
                    float2 cv;
                    cv.x = acc[mf][nf][half * 2 + 0] + bia;
                    cv.y = acc[mf][nf][half * 2 + 1] + bia;
                    *(float2*)(crow + cc) = cv;
                    s += cv.x + cv.y;
                    q += cv.x * cv.x + cv.y * cv.y;
                }
                if (stats) {
                    #pragma unroll
                    for (int o = 1; o < 4; o <<= 1) {
                        s += __shfl_xor_sync(0xffffffffu, s, o);
                        q += __shfl_xor_sync(0xffffffffu, q, o);
                    }
                    if (tq == 0) {
                        atomicAdd_block(&bnS[r - m0], s);
                        atomicAdd_block(&bnQ[r - m0], q);
                    }
                }
            }
        }
    }
    if (stats) {
        __syncthreads();
        if (tid < 128) {
            atomicAdd(&stats[m0 + tid], bnS[tid]);
            atomicAdd(&stats[512 + m0 + tid], bnQ[tid]);
        }
    }
}

// ---------------- small-M (M=32) TF32 GEMM ----------------
#define SA_STG (32*GAPITCH)
#define SB_STG (32*GBPITCH)
#define GEMM32_SMEM (2*(SA_STG+SB_STG)*4)

__global__ void __launch_bounds__(256, 2) mma_gemm32_kernel(
    const float* __restrict__ A, int lda,
    const float* __restrict__ Bm, long long bStride,
    const float* __restrict__ bias,
    float* __restrict__ Cm, long long cStride,
    int K, int N)
{
    extern __shared__ float sm[];
    float* sA = sm;
    float* sB = sm + 2 * SA_STG;
    const uint32_t sA_u = (uint32_t)__cvta_generic_to_shared(sA);
    const uint32_t sB_u = (uint32_t)__cvta_generic_to_shared(sB);

    const int tid  = threadIdx.x;
    const int warp = tid >> 5, lane = tid & 31;
    const int g = lane >> 2, tq = lane & 3;
    const int wn = warp * 32;
    const int n0 = blockIdx.x * 256;
    const float* Bb = Bm + (long long)blockIdx.z * bStride;
    float* Cb       = Cm + (long long)blockIdx.z * cStride;

    const int ar = tid >> 3, ac16 = tid & 7;
    const float* aSrc = A + (long long)ar * lda + ac16 * 4;
    const uint32_t adst = (ar * GAPITCH + ac16 * 4) * 4;

    int brow[8], bdst[8];
    const float* bSrc[8];
    #pragma unroll
    for (int i = 0; i < 8; i++) {
        int ch = tid + 256 * i;
        brow[i] = ch >> 6;
        int c16 = ch & 63;
        bdst[i] = (brow[i] * GBPITCH + c16 * 4) * 4;
        bSrc[i] = Bb + (long long)brow[i] * N + n0 + c16 * 4;
    }

    const int nch = K >> 5;

    cp16(sA_u + adst, aSrc, 16);
    #pragma unroll
    for (int i = 0; i < 8; i++) cp16(sB_u + bdst[i], bSrc[i], 16);
    asm volatile("cp.async.commit_group;");

    float acc[2][4][4];
    #pragma unroll
    for (int mf = 0; mf < 2; mf++)
        #pragma unroll
        for (int nf = 0; nf < 4; nf++)
            #pragma unroll
            for (int i = 0; i < 4; i++) acc[mf][nf][i] = 0.0f;

    for (int c = 0; c < nch; c++) {
        if (c + 1 < nch) {
            int s = (c + 1) & 1;
            int kc = (c + 1) * 32;
            uint32_t da = sA_u + (s * SA_STG) * 4;
            uint32_t db = sB_u + (s * SB_STG) * 4;
            cp16(da + adst, aSrc + kc, 16);
            #pragma unroll
            for (int i = 0; i < 8; i++)
                cp16(db + bdst[i], bSrc[i] + (long long)kc * N, 16);
            asm volatile("cp.async.commit_group;");
            asm volatile("cp.async.wait_group 1;");
        } else {
            asm volatile("cp.async.wait_group 0;");
        }
        __syncthreads();

        const float* As_ = sA + (c & 1) * SA_STG;
        const float* Bs_ = sB + (c & 1) * SB_STG;
        #pragma unroll
        for (int ks = 0; ks < 4; ks++) {
            const int k1 = ks * 8 + tq, k2 = k1 + 4;
            uint32_t afr[2][4];
            #pragma unroll
            for (int mf = 0; mf < 2; mf++) {
                int mb = mf * 16 + g;
                afr[mf][0] = __float_as_uint(As_[mb * GAPITCH + k1]);
                afr[mf][1] = __float_as_uint(As_[(mb + 8) * GAPITCH + k1]);
                afr[mf][2] = __float_as_uint(As_[mb * GAPITCH + k2]);
                afr[mf][3] = __float_as_uint(As_[(mb + 8) * GAPITCH + k2]);
            }
            #pragma unroll
            for (int nf = 0; nf < 4; nf++) {
                int nb = wn + nf * 8 + g;
                uint32_t b0 = __float_as_uint(Bs_[k1 * GBPITCH + nb]);
                uint32_t b1 = __float_as_uint(Bs_[k2 * GBPITCH + nb]);
                #pragma unroll
                for (int mf = 0; mf < 2; mf++)
                    mma_tf32(acc[mf][nf], afr[mf], b0, b1);
            }
        }
        __syncthreads();
    }

    #pragma unroll
    for (int mf = 0; mf < 2; mf++) {
        #pragma unroll
        for (int half = 0; half < 2; half++) {
            int r = mf * 16 + g + half * 8;
            float bia = bias ? bias[r] : 0.0f;
            float* crow = Cb + (long long)r * N;
            #pragma unroll
            for (int nf = 0; nf < 4; nf++) {
                int cc = n0 + wn + nf * 8 + 2 * tq;
                float2 cv;
                cv.x = acc[mf][nf][half * 2 + 0] + bia;
                cv.y = acc[mf][nf][half * 2 + 1] + bia;
                *(float2*)(crow + cc) = cv;
            }
        }
    }
}

// ---------------- merged tiled 96x96 plane transpose (k then v planes) ----------------
__global__ void transpose96_kernel(const float* __restrict__ inK, float* __restrict__ outK,
                                   int nKPlanes,
                                   const float* __restrict__ inV, float* __restrict__ outV) {
    __shared__ float tile[32][33];
    int p = blockIdx.z;
    const float* in;
    float* out;
    if (p < nKPlanes) { in = inK + (long)p * 9216; out = outK + (long)p * 9216; }
    else { int q = p - nKPlanes; in = inV + (long)q * 9216; out = outV + (long)q * 9216; }
    int x0 = blockIdx.x * 32, y0 = blockIdx.y * 32;
    int tx = threadIdx.x, ty = threadIdx.y;
    #pragma unroll
    for (int k = 0; k < 4; k++)
        tile[ty + 8*k][tx] = in[(long)(y0 + ty + 8*k) * 96 + x0 + tx];
    __syncthreads();
    #pragma unroll
    for (int k = 0; k < 4; k++)
        out[(long)(x0 + ty + 8*k) * 96 + y0 + tx] = tile[tx][ty + 8*k];
}

// ---------------- merged qk logits: z=0 -> eH (diag), z=1 -> eW ----------------
__global__ void __launch_bounds__(256) qk_kernel(const float* __restrict__ qt,
                                                 const float* __restrict__ kt,
                                                 const float* __restrict__ qb,
                                                 const float* __restrict__ kb,
                                                 float* __restrict__ attH,
                                                 float* __restrict__ attW) {
    int x = blockIdx.x, b = blockIdx.y;
    int diag = (blockIdx.z == 0);
    const float* qsrc = diag ? qt : qb;
    const float* ksrc = diag ? kt : kb;
    float* attX = diag ? attH : attW;
    __shared__ float Qs[32][97], Ks[32][97];
    int tid = threadIdx.x;
    for (int idx = tid; idx < 3072; idx += 256) {
        int ci = idx / 96, inner = idx % 96;
        long off = ((long)((b * 32 + ci) * 96 + x)) * 96 + inner;
        Qs[ci][inner] = qsrc[off];
        Ks[ci][inner] = ksrc[off];
    }
    __syncthreads();
    float* ab = attX + ((long)(b * 96 + x)) * 9216;
    for (int idx = tid; idx < 2304; idx += 256) {
        int o = idx / 24;
        int P0 = (idx % 24) * 4;
        float acc[4];
        #pragma unroll
        for (int j = 0; j < 4; j++) acc[j] = (diag && (P0 + j == o)) ? NEG_INF_F : 0.0f;
        #pragma unroll
        for (int c = 0; c < 32; c++) {
            float qv = Qs[c][o];
            #pragma unroll
            for (int j = 0; j < 4; j++) acc[j] += qv * Ks[c][P0 + j];
        }
        *(float4*)(ab + o * 96 + P0) = make_float4(acc[0], acc[1], acc[2], acc[3]);
    }
}

// ---------------- joint softmax ----------------
__global__ void softmax2_kernel(float* __restrict__ attH, float* __restrict__ attW) {
    int row = blockIdx.x * 8 + threadIdx.y;
    int b = row / 9216, rem = row % 9216, h = rem / 96, w = rem % 96;
    float* pH = attH + ((long)(b * 96 + w) * 96 + h) * 96;
    float* pW = attW + ((long)(b * 96 + h) * 96 + w) * 96;
    int lane = threadIdx.x;
    float v[6];
    #pragma unroll
    for (int j = 0; j < 3; j++) v[j]     = pH[j * 32 + lane];
    #pragma unroll
    for (int j = 0; j < 3; j++) v[3 + j] = pW[j * 32 + lane];
    float m = -3.0e38f;
    #pragma unroll
    for (int j = 0; j < 6; j++) m = fmaxf(m, v[j]);
    #pragma unroll
    for (int o = 16; o > 0; o >>= 1) m = fmaxf(m, __shfl_xor_sync(0xffffffffu, m, o));
    float s = 0.0f;
    #pragma unroll
    for (int j = 0; j < 6; j++) { v[j] = expf(v[j] - m); s += v[j]; }
    #pragma unroll
    for (int o = 16; o > 0; o >>= 1) s += __shfl_xor_sync(0xffffffffu, s, o);
    float inv = 1.0f / s;
    #pragma unroll
    for (int j = 0; j < 3; j++) pH[j * 32 + lane] = v[j] * inv;
    #pragma unroll
    for (int j = 0; j < 3; j++) pW[j * 32 + lane] = v[3 + j] * inv;
}

// ---------------- merged P*V via tensor cores: z=0 -> H dir, z=1 -> W dir ----------------
#define PV_SMEM ((96*100 + 128*100) * 4)
__global__ void __launch_bounds__(256) pv_mma_kernel(const float* __restrict__ vt,
                                                     const float* __restrict__ vb,
                                                     const float* __restrict__ attH,
                                                     const float* __restrict__ attW,
                                                     float* __restrict__ ohb,
                                                     float* __restrict__ owb) {
    extern __shared__ float sh[];
    float* Ah = sh;              // [96][100]
    float* Vs = sh + 96 * 100;   // [128][100]
    int x = blockIdx.x, b = blockIdx.y;
    int dirH = (blockIdx.z == 0);
    const float* Vsrc = dirH ? vt : vb;
    const float* attX = dirH ? attH : attW;
    float* outX       = dirH ? ohb : owb;
    int tid = threadIdx.x;
    int warp = tid >> 5, lane = tid & 31;
    int g = lane >> 2, tq = lane & 3;
    int wm = (warp >> 2) * 64;
    int wn = (warp & 3) * 24;

    const float* ab = attX + ((long)(b * 96 + x)) * 9216;
    for (int i4 = tid; i4 < 96 * 24; i4 += 256) {
        int h = i4 / 24, f = i4 % 24;
        float4 v4 = *(const float4*)(ab + i4 * 4);
        *(float4*)&Ah[h * 100 + f * 4] = v4;
    }

    #pragma unroll
    for (int half = 0; half < 2; half++) {
        const float* vbp = Vsrc + (((long)(b * 256 + half * 128)) * 96 + x) * 96;
        for (int i4 = tid; i4 < 128 * 24; i4 += 256) {
            int ci = i4 / 24, f = i4 % 24;
            float4 v4 = *(const float4*)(vbp + (long)ci * 9216 + f * 4);
            *(float4*)&Vs[ci * 100 + f * 4] = v4;
        }
        __syncthreads();

        float acc[4][3][4];
        #pragma unroll
        for (int mf = 0; mf < 4; mf++)
            #pragma unroll
            for (int nf = 0; nf < 3; nf++)
                #pragma unroll
                for (int i = 0; i < 4; i++) acc[mf][nf][i] = 0.0f;

        #pragma unroll
        for (int ks = 0; ks < 12; ks++) {
            int k1 = ks * 8 + tq, k2 = k1 + 4;
            uint32_t afr[4][4];
            #pragma unroll
            for (int mf = 0; mf < 4; mf++) {
                int mb = wm + mf * 16 + g;
                afr[mf][0] = __float_as_uint(Vs[mb * 100 + k1]);
                afr[mf][1] = __float_as_uint(Vs[(mb + 8) * 100 + k1]);
                afr[mf][2] = __float_as_uint(Vs[mb * 100 + k2]);
                afr[mf][3] = __float_as_uint(Vs[(mb + 8) * 100 + k2]);
            }
            #pragma unroll
            for (int nf = 0; nf < 3; nf++) {
                int nb = wn + nf * 8 + g;
                uint32_t b0 = __float_as_uint(Ah[nb * 100 + k1]);
                uint32_t b1 = __float_as_uint(Ah[nb * 100 + k2]);
                #pragma unroll
                for (int mf = 0; mf < 4; mf++)
                    mma_tf32(acc[mf][nf], afr[mf], b0, b1);
            }
        }
        __syncthreads();

        #pragma unroll
        for (int mf = 0; mf < 4; mf++) {
            #pragma unroll
            for (int hm = 0; hm < 2; hm++) {
                int c = half * 128 + wm + mf * 16 + g + hm * 8;
                float* orow = outX + (((long)(b * 256 + c)) * 96 + x) * 96;
                #pragma unroll
                for (int nf = 0; nf < 3; nf++) {
                    int col = wn + nf * 8 + 2 * tq;
                    float2 cv;
                    cv.x = acc[mf][nf][hm * 2 + 0];
                    cv.y = acc[mf][nf][hm * 2 + 1];
                    *(float2*)(orow + col) = cv;
                }
            }
        }
    }
}

// ---------------- combine ----------------
__global__ void combine_kernel(const float* __restrict__ ow, const float* __restrict__ ohT,
                               const float* __restrict__ resid, const float* __restrict__ gamma_p,
                               float* __restrict__ dst) {
    __shared__ float tile[32][33];
    int h0 = blockIdx.x * 32, w0 = blockIdx.y * 32;
    long base = (long)blockIdx.z * 9216;
    int tx = threadIdx.x, ty = threadIdx.y;
    float g = *gamma_p;
    #pragma unroll
    for (int k = 0; k < 4; k++)
        tile[ty + 8*k][tx] = ohT[base + (long)(w0 + ty + 8*k) * 96 + h0 + tx];
    __syncthreads();
    #pragma unroll
    for (int k = 0; k < 4; k++) {
        long idx = base + (long)(h0 + ty + 8*k) * 96 + w0 + tx;
        dst[idx] = g * (ow[idx] + tile[tx][ty + 8*k]) + resid[idx];
    }
}

// ---------------- batchnorm apply (stats from fused sums) ----------------
__global__ void bn_apply_kernel(float4* __restrict__ x,
                                const float* __restrict__ stats,
                                const float* __restrict__ scale, const float* __restrict__ bias) {
    const float invN = 1.0f / 73728.0f;
    long total = 8L * 512 * 2304;
    for (long idx = (long)blockIdx.x * blockDim.x + threadIdx.x; idx < total;
         idx += (long)gridDim.x * blockDim.x) {
        int c = (int)((idx / 2304) % 512);
        float mu = stats[c] * invN;
        float var = stats[512 + c] * invN - mu * mu;
        float rs = rsqrtf(var + 1e-5f);
        float sc = scale[c], bi = bias[c];
        float4 v = x[idx];
        v.x = fmaxf((v.x - mu) * rs * sc + bi, 0.0f);
        v.y = fmaxf((v.y - mu) * rs * sc + bi, 0.0f);
        v.z = fmaxf((v.z - mu) * rs * sc + bi, 0.0f);
        v.w = fmaxf((v.w - mu) * rs * sc + bi, 0.0f);
        x[idx] = v;
    }
}

// ---------------- host ----------------
static inline void launch_gemm(const float* A, int lda, const float* Bm, long long bs,
                               const float* bias, float* Cm, long long cs,
                               int M, int K, int N) {
    dim3 grid(N / 256, (M + 127) / 128, 8);
    mma_gemm_kernel<<<grid, 256, GEMM_SMEM>>>(A, lda, Bm, bs, nullptr, 0, 1 << 30,
                                              bias, Cm, cs, M, K, N, nullptr);
}

extern "C" void kernel_launch(void* const* d_in, const int* in_sizes, int n_in,
                              void* d_out, int out_size) {
    const float* low      = (const float*)d_in[0];
    const float* high     = (const float*)d_in[1];
    const float* conv1_w  = (const float*)d_in[2];
    const float* conv1_b  = (const float*)d_in[3];
    const float* conv2_w  = (const float*)d_in[4];
    const float* conv2_b  = (const float*)d_in[5];
    const float* q_w      = (const float*)d_in[6];
    const float* q_b      = (const float*)d_in[7];
    const float* k_w      = (const float*)d_in[8];
    const float* k_b      = (const float*)d_in[9];
    const float* v_w      = (const float*)d_in[10];
    const float* v_b      = (const float*)d_in[11];
    const float* gamma    = (const float*)d_in[12];
    const float* bw       = (const float*)d_in[13];
    const float* bn_scale = (const float*)d_in[14];
    const float* bn_bias  = (const float*)d_in[15];
    float* out = (float*)d_out;

    float *hf, *qf, *vf, *vf2, *qb, *kb, *vb, *qt, *kt, *vt;
    float *attH, *attW, *ohb, *owb, *statsp;
    cudaGetSymbolAddress((void**)&hf,   g_hf);
    cudaGetSymbolAddress((void**)&qf,   g_qf);
    cudaGetSymbolAddress((void**)&vf,   g_vf);
    cudaGetSymbolAddress((void**)&vf2,  g_vf2);
    cudaGetSymbolAddress((void**)&qb,   g_q);
    cudaGetSymbolAddress((void**)&kb,   g_k);
    cudaGetSymbolAddress((void**)&vb,   g_v);
    cudaGetSymbolAddress((void**)&qt,   g_qt);
    cudaGetSymbolAddress((void**)&kt,   g_kt);
    cudaGetSymbolAddress((void**)&vt,   g_vt);
    cudaGetSymbolAddress((void**)&attH, g_attH);
    cudaGetSymbolAddress((void**)&attW, g_attW);
    cudaGetSymbolAddress((void**)&ohb,  g_oh);
    cudaGetSymbolAddress((void**)&owb,  g_ow);
    cudaGetSymbolAddress((void**)&statsp, g_stats);

    cudaFuncSetAttribute(mma_gemm_kernel,   cudaFuncAttributeMaxDynamicSharedMemorySize, GEMM_SMEM);
    cudaFuncSetAttribute(mma_gemm32_kernel, cudaFuncAttributeMaxDynamicSharedMemorySize, GEMM32_SMEM);
    cudaFuncSetAttribute(pv_mma_kernel,     cudaFuncAttributeMaxDynamicSharedMemorySize, PV_SMEM);

    // 1. upsample (+ zero BN stats accumulators)
    resize_kernel<<<2048, 256>>>(high, hf, statsp);

    // 2. projections
    launch_gemm(conv1_w, 512, low, 512LL * 9216, conv1_b, qf, 256LL * 9216, 256, 512, 9216);
    launch_gemm(conv2_w, 512, hf, 512LL * 9216, conv2_b, vf, 256LL * 9216, 256, 512, 9216);
    mma_gemm32_kernel<<<dim3(36, 1, 8), 256, GEMM32_SMEM>>>(
        q_w, 256, qf, 256LL * 9216, q_b, qb, 32LL * 9216, 256, 9216);
    transpose96_kernel<<<dim3(3, 3, 8 * 32), dim3(32, 8)>>>(qb, qt, 8 * 32, qb, qt);

    for (int it = 0; it < 2; it++) {
        const float* src = it ? vf2 : vf;
        float* dstp      = it ? vf  : vf2;
        mma_gemm32_kernel<<<dim3(36, 1, 8), 256, GEMM32_SMEM>>>(
            k_w, 256, src, 256LL * 9216, k_b, kb, 32LL * 9216, 256, 9216);
        launch_gemm(v_w, 256, src, 256LL * 9216, v_b, vb, 256LL * 9216, 256, 256, 9216);
        transpose96_kernel<<<dim3(3, 3, 8 * 32 + 8 * 256), dim3(32, 8)>>>(kb, kt, 8 * 32, vb, vt);
        qk_kernel<<<dim3(96, 8, 2), 256>>>(qt, kt, qb, kb, attH, attW);
        softmax2_kernel<<<9216, dim3(32, 8)>>>(attH, attW);
        pv_mma_kernel<<<dim3(96, 8, 2), 256, PV_SMEM>>>(vt, vb, attH, attW, ohb, owb);
        combine_kernel<<<dim3(3, 3, 8 * 256), dim3(32, 8)>>>(owb, ohb, src, gamma, dstp);
    }

    // bottleneck: single K=768 pass + fused BN stats
    {
        dim3 grid(9216 / 256, 512 / 128, 8);
        mma_gemm_kernel<<<grid, 256, GEMM_SMEM>>>(
            bw, 768, vf, 256LL * 9216, hf, 512LL * 9216, 256,
            nullptr, out, 512LL * 9216, 512, 768, 9216, statsp);
    }

    // batchnorm + relu (mean/rstd derived inline from fused sums)
    bn_apply_kernel<<<4608, 256>>>((float4*)out, statsp, bn_scale, bn_bias);
}